// round 9
// baseline (speedup 1.0000x reference)
#include <cuda_runtime.h>
#include <cuda_bf16.h>
#include <math.h>

// Problem constants
#define B_   32
#define T_   128
#define H_   768
#define IN_  256
#define H2_  1536

// exp(-1/20)
#define ALPHA_   0.951229424500714f
#define OMA_     0.048770575499286f
#define DTR_     0.951229424500714f
#define OMD_     0.048770575499286f
#define ETA_     0.1f
#define CIKV_    0.02f

// Output offsets (floats): mem | keys | vals
#define OUT_MEM_   0
#define OUT_KEYS_  18874368
#define OUT_VALS_  22020096

// Scratch (f32)
__device__ float g_i[B_ * T_ * H2_];
__device__ float g_Apart[6 * B_ * T_ * T_];

// Pre-split bf16 hi/lo operand arrays
__device__ __nv_bfloat16 g_xh[B_ * T_ * IN_],  g_xl[B_ * T_ * IN_];
__device__ __nv_bfloat16 g_Wh[H2_ * IN_],      g_Wl[H2_ * IN_];
__device__ __nv_bfloat16 g_keyh[B_ * T_ * H_], g_keyl[B_ * T_ * H_];
__device__ __nv_bfloat16 g_ktrh[B_ * T_ * H_], g_ktrl[B_ * T_ * H_];
__device__ __nv_bfloat16 g_vtrh[B_ * T_ * H_], g_vtrl[B_ * T_ * H_];

__device__ __forceinline__ float tanh_fast(float x) {
    float y;
    asm("tanh.approx.f32 %0, %1;" : "=f"(y) : "f"(x));
    return y;
}
__device__ __forceinline__ void split_bf16(float v, __nv_bfloat16& hi, __nv_bfloat16& lo) {
    hi = __float2bfloat16(v);
    lo = __float2bfloat16(v - __bfloat162float(hi));
}

// ---------------------------------------------------------------------------
// mma.sync helpers
// ---------------------------------------------------------------------------
__device__ __forceinline__ void ldsm_x4(unsigned addr, unsigned& r0, unsigned& r1,
                                        unsigned& r2, unsigned& r3) {
    asm volatile("ldmatrix.sync.aligned.m8n8.x4.shared.b16 {%0,%1,%2,%3}, [%4];"
                 : "=r"(r0), "=r"(r1), "=r"(r2), "=r"(r3) : "r"(addr));
}
__device__ __forceinline__ void ldsm_x4t(unsigned addr, unsigned& r0, unsigned& r1,
                                         unsigned& r2, unsigned& r3) {
    asm volatile("ldmatrix.sync.aligned.m8n8.x4.trans.shared.b16 {%0,%1,%2,%3}, [%4];"
                 : "=r"(r0), "=r"(r1), "=r"(r2), "=r"(r3) : "r"(addr));
}
__device__ __forceinline__ void mma16816(float* c, unsigned a0, unsigned a1,
                                         unsigned a2, unsigned a3,
                                         unsigned b0, unsigned b1) {
    asm volatile(
        "mma.sync.aligned.m16n8k16.row.col.f32.bf16.bf16.f32 "
        "{%0,%1,%2,%3}, {%4,%5,%6,%7}, {%8,%9}, {%0,%1,%2,%3};"
        : "+f"(c[0]), "+f"(c[1]), "+f"(c[2]), "+f"(c[3])
        : "r"(a0), "r"(a1), "r"(a2), "r"(a3), "r"(b0), "r"(b1));
}

// cp.async helpers
__device__ __forceinline__ void cp16(unsigned dst, const void* src) {
    asm volatile("cp.async.cg.shared.global [%0], [%1], 16;" :: "r"(dst), "l"(src));
}
#define CP_COMMIT() asm volatile("cp.async.commit_group;")
#define CP_WAIT0()  asm volatile("cp.async.wait_group 0;" ::: "memory")

#define SRM 40    // smem stride (halves) row-major tiles (128 rows x 32 k)
#define SKM 136   // smem stride (halves) k-major tiles (32 k x 128 m)
#define RM_BUF_HALVES (128 * SRM)           // 5120
#define RM_STAGE_HALVES (4 * RM_BUF_HALVES) // Ah,Al,Bh,Bl
#define KM_BUF_HALVES (32 * SKM)            // 4352
#define KM_STAGE_HALVES (4 * KM_BUF_HALVES)

// Copy one row-major 128x32 bf16 tile pair (hi,lo) into smem via cp.async.
__device__ __forceinline__ void cpa_rm(unsigned dsth, const __nv_bfloat16* srch,
                                       unsigned dstl, const __nv_bfloat16* srcl,
                                       int ld, int tid)
{
#pragma unroll
    for (int l = 0; l < 2; l++) {
        int c = tid + l * 256;
        int row = c >> 2;
        int q   = c & 3;
        unsigned doff = (unsigned)(row * SRM * 2 + q * 16);
        const char* so = (const char*)srch + (size_t)row * ld * 2 + q * 16;
        cp16(dsth + doff, so);
        const char* so2 = (const char*)srcl + (size_t)row * ld * 2 + q * 16;
        cp16(dstl + doff, so2);
    }
}
// Copy one k-major 32x128 bf16 tile pair into smem.
__device__ __forceinline__ void cpa_km(unsigned dsth, const __nv_bfloat16* srch,
                                       unsigned dstl, const __nv_bfloat16* srcl,
                                       int ld, int tid)
{
#pragma unroll
    for (int l = 0; l < 2; l++) {
        int c = tid + l * 256;
        int row = c >> 4;
        int q   = c & 15;
        unsigned doff = (unsigned)(row * SKM * 2 + q * 16);
        const char* so = (const char*)srch + (size_t)row * ld * 2 + q * 16;
        cp16(dsth + doff, so);
        const char* so2 = (const char*)srcl + (size_t)row * ld * 2 + q * 16;
        cp16(dstl + doff, so2);
    }
}

// One BK=32 compute step: row-major smem tiles [128][SRM], no-trans ldmatrix.
__device__ __forceinline__ void mma_step_rm(
    unsigned bAh, unsigned bAl, unsigned bBh, unsigned bBl,
    int wm, int wn, int lane, float acc[4][4][4])
{
    const int lr = lane & 15;
    const int kh = (lane >> 4) * 8;
#pragma unroll
    for (int ks = 0; ks < 32; ks += 16) {
        unsigned ah[4][4], al[4][4], bh[4][2], bl[4][2];
#pragma unroll
        for (int i = 0; i < 4; i++) {
            unsigned off = 2u * ((wm * 64 + i * 16 + lr) * SRM + ks + kh);
            ldsm_x4(bAh + off, ah[i][0], ah[i][1], ah[i][2], ah[i][3]);
            ldsm_x4(bAl + off, al[i][0], al[i][1], al[i][2], al[i][3]);
        }
#pragma unroll
        for (int p = 0; p < 2; p++) {
            unsigned off = 2u * ((wn * 32 + p * 16 + lr) * SRM + ks + kh);
            unsigned r0, r1, r2, r3;
            ldsm_x4(bBh + off, r0, r1, r2, r3);
            bh[p * 2 + 0][0] = r0; bh[p * 2 + 0][1] = r2;
            bh[p * 2 + 1][0] = r1; bh[p * 2 + 1][1] = r3;
            ldsm_x4(bBl + off, r0, r1, r2, r3);
            bl[p * 2 + 0][0] = r0; bl[p * 2 + 0][1] = r2;
            bl[p * 2 + 1][0] = r1; bl[p * 2 + 1][1] = r3;
        }
#pragma unroll
        for (int i = 0; i < 4; i++)
#pragma unroll
            for (int j = 0; j < 4; j++) {
                mma16816(acc[i][j], ah[i][0], ah[i][1], ah[i][2], ah[i][3],
                         bh[j][0], bh[j][1]);
                mma16816(acc[i][j], ah[i][0], ah[i][1], ah[i][2], ah[i][3],
                         bl[j][0], bl[j][1]);
                mma16816(acc[i][j], al[i][0], al[i][1], al[i][2], al[i][3],
                         bh[j][0], bh[j][1]);
            }
    }
}

// One BK=32 compute step: k-major smem tiles [32][SKM], trans ldmatrix.
__device__ __forceinline__ void mma_step_km(
    unsigned bAh, unsigned bAl, unsigned bBh, unsigned bBl,
    int wm, int wn, int lane, float acc[4][4][4])
{
    const int krow = (lane & 7) + ((lane >> 4) << 3);
    const int mcol = ((lane >> 3) & 1) * 8;
#pragma unroll
    for (int ks = 0; ks < 32; ks += 16) {
        unsigned ah[4][4], al[4][4], bh[4][2], bl[4][2];
#pragma unroll
        for (int i = 0; i < 4; i++) {
            unsigned off = 2u * ((ks + krow) * SKM + wm * 64 + i * 16 + mcol);
            ldsm_x4t(bAh + off, ah[i][0], ah[i][1], ah[i][2], ah[i][3]);
            ldsm_x4t(bAl + off, al[i][0], al[i][1], al[i][2], al[i][3]);
        }
#pragma unroll
        for (int p = 0; p < 2; p++) {
            unsigned off = 2u * ((ks + krow) * SKM + wn * 32 + p * 16 + mcol);
            unsigned r0, r1, r2, r3;
            ldsm_x4t(bBh + off, r0, r1, r2, r3);
            bh[p * 2 + 0][0] = r0; bh[p * 2 + 0][1] = r2;
            bh[p * 2 + 1][0] = r1; bh[p * 2 + 1][1] = r3;
            ldsm_x4t(bBl + off, r0, r1, r2, r3);
            bl[p * 2 + 0][0] = r0; bl[p * 2 + 0][1] = r2;
            bl[p * 2 + 1][0] = r1; bl[p * 2 + 1][1] = r3;
        }
#pragma unroll
        for (int i = 0; i < 4; i++)
#pragma unroll
            for (int j = 0; j < 4; j++) {
                mma16816(acc[i][j], ah[i][0], ah[i][1], ah[i][2], ah[i][3],
                         bh[j][0], bh[j][1]);
                mma16816(acc[i][j], ah[i][0], ah[i][1], ah[i][2], ah[i][3],
                         bl[j][0], bl[j][1]);
                mma16816(acc[i][j], al[i][0], al[i][1], al[i][2], al[i][3],
                         bh[j][0], bh[j][1]);
            }
    }
}

// Epilogue: write 4x4 m16n8 tiles to gmem, scaled.
__device__ __forceinline__ void epilogue(float* dst, int ldc, float scale,
                                         int wm, int wn, int lane,
                                         float acc[4][4][4])
{
    const int r0 = lane >> 2;
    const int c0 = (lane & 3) * 2;
#pragma unroll
    for (int i = 0; i < 4; i++)
#pragma unroll
        for (int j = 0; j < 4; j++) {
            int row = wm * 64 + i * 16 + r0;
            int col = wn * 32 + j * 8 + c0;
            float2 v0 = make_float2(scale * acc[i][j][0], scale * acc[i][j][1]);
            float2 v1 = make_float2(scale * acc[i][j][2], scale * acc[i][j][3]);
            *(float2*)&dst[row * ldc + col] = v0;
            *(float2*)&dst[(row + 8) * ldc + col] = v1;
        }
}

// ---------------------------------------------------------------------------
// K0: pre-split x and W into hi/lo bf16
// ---------------------------------------------------------------------------
#define XN_ (B_ * T_ * IN_)   // 1048576
#define WN_ (H2_ * IN_)       // 393216

__global__ __launch_bounds__(256) void k0_convert(
    const float* __restrict__ x, const float* __restrict__ W)
{
    int i4 = (blockIdx.x * 256 + threadIdx.x) * 4;
    const float* src;
    __nv_bfloat16 *dh, *dl;
    int off;
    if (i4 < XN_) {
        src = x; dh = g_xh; dl = g_xl; off = i4;
    } else if (i4 < XN_ + WN_) {
        src = W; dh = g_Wh; dl = g_Wl; off = i4 - XN_;
    } else return;
    float4 v = *(const float4*)&src[off];
    __nv_bfloat16 h0, l0, h1, l1, h2, l2, h3, l3;
    split_bf16(v.x, h0, l0); split_bf16(v.y, h1, l1);
    split_bf16(v.z, h2, l2); split_bf16(v.w, h3, l3);
    dh[off + 0] = h0; dh[off + 1] = h1; dh[off + 2] = h2; dh[off + 3] = h3;
    dl[off + 0] = l0; dl[off + 1] = l1; dl[off + 2] = l2; dl[off + 3] = l3;
}

// ---------------------------------------------------------------------------
// K1: g_i[m][n] = sum_k x[m][k]*W[n][k]   M=4096 N=1536 K=256 (NK=8)
//     cp.async double-buffered. Dyn smem 80KB.
// ---------------------------------------------------------------------------
__global__ __launch_bounds__(256, 2) void k1_gemm_in()
{
    extern __shared__ __nv_bfloat16 dyn[];
    const int m0 = blockIdx.y * 128;
    const int n0 = blockIdx.x * 128;
    const int tid = threadIdx.x;
    const int warp = tid >> 5, lane = tid & 31;
    const int wm = warp >> 2, wn = warp & 3;

    unsigned sb = (unsigned)__cvta_generic_to_shared(dyn);

    float acc[4][4][4];
#pragma unroll
    for (int i = 0; i < 4; i++)
#pragma unroll
        for (int j = 0; j < 4; j++)
#pragma unroll
            for (int r = 0; r < 4; r++) acc[i][j][r] = 0.f;

    const __nv_bfloat16* Ah = &g_xh[(size_t)m0 * IN_];
    const __nv_bfloat16* Al = &g_xl[(size_t)m0 * IN_];
    const __nv_bfloat16* Bh = &g_Wh[(size_t)n0 * IN_];
    const __nv_bfloat16* Bl = &g_Wl[(size_t)n0 * IN_];

#define NK1 8
    {
        unsigned s0 = sb;
        cpa_rm(s0, Ah, s0 + RM_BUF_HALVES * 2u, Al, IN_, tid);
        cpa_rm(s0 + RM_BUF_HALVES * 4u, Bh, s0 + RM_BUF_HALVES * 6u, Bl, IN_, tid);
        CP_COMMIT();
    }
    for (int k = 0; k < NK1; k++) {
        CP_WAIT0();
        __syncthreads();
        if (k + 1 < NK1) {
            unsigned s1 = sb + (unsigned)(((k + 1) & 1) * RM_STAGE_HALVES) * 2u;
            cpa_rm(s1, Ah + (k + 1) * 32, s1 + RM_BUF_HALVES * 2u, Al + (k + 1) * 32, IN_, tid);
            cpa_rm(s1 + RM_BUF_HALVES * 4u, Bh + (k + 1) * 32,
                   s1 + RM_BUF_HALVES * 6u, Bl + (k + 1) * 32, IN_, tid);
            CP_COMMIT();
        }
        unsigned s = sb + (unsigned)((k & 1) * RM_STAGE_HALVES) * 2u;
        mma_step_rm(s, s + RM_BUF_HALVES * 2u, s + RM_BUF_HALVES * 4u,
                    s + RM_BUF_HALVES * 6u, wm, wn, lane, acc);
    }
    epilogue(&g_i[(size_t)m0 * H2_ + n0], H2_, 1.f, wm, wn, lane, acc);
}

// ---------------------------------------------------------------------------
// K2: key-side elementwise scan; writes keys (f32 out) + hi/lo bf16 key/ktr
// ---------------------------------------------------------------------------
__global__ __launch_bounds__(256) void k2_scan_key(float* __restrict__ out)
{
    const int b  = blockIdx.x / 3;
    const int h  = (blockIdx.x % 3) * 256 + threadIdx.x;

    const float* ik = &g_i[(b * T_) * H2_ + h];
    const int base = (b * T_) * H_ + h;
    float* keyso = &out[OUT_KEYS_ + base];

    float kv = 0.f, ktr = 0.f;
#pragma unroll 4
    for (int t = 0; t < T_; t++) {
        kv = ALPHA_ * kv + OMA_ * ik[t * H2_];
        float key = tanh_fast(kv);
        ktr = DTR_ * ktr + OMD_ * key;
        keyso[t * H_] = key;
        __nv_bfloat16 hh, ll;
        split_bf16(key, hh, ll);
        g_keyh[base + t * H_] = hh; g_keyl[base + t * H_] = ll;
        split_bf16(ktr, hh, ll);
        g_ktrh[base + t * H_] = hh; g_ktrl[base + t * H_] = ll;
    }
}

// ---------------------------------------------------------------------------
// K3: Apart[p][b][t][s] = sum_{k in chunk p} key[b,t,k]*ktr[b,s,k]
//     grid (6,32). NK=4. cp.async double-buffered.
// ---------------------------------------------------------------------------
__global__ __launch_bounds__(256, 2) void k3_gemm_A()
{
    extern __shared__ __nv_bfloat16 dyn[];
    const int p = blockIdx.x;
    const int b = blockIdx.y;
    const int tid = threadIdx.x;
    const int warp = tid >> 5, lane = tid & 31;
    const int wm = warp >> 2, wn = warp & 3;

    unsigned sb = (unsigned)__cvta_generic_to_shared(dyn);

    const size_t base = (size_t)b * T_ * H_ + p * 128;
    const __nv_bfloat16* Ah = &g_keyh[base];
    const __nv_bfloat16* Al = &g_keyl[base];
    const __nv_bfloat16* Bh = &g_ktrh[base];
    const __nv_bfloat16* Bl = &g_ktrl[base];

    float acc[4][4][4];
#pragma unroll
    for (int i = 0; i < 4; i++)
#pragma unroll
        for (int j = 0; j < 4; j++)
#pragma unroll
            for (int r = 0; r < 4; r++) acc[i][j][r] = 0.f;

#define NK3 4
    {
        unsigned s0 = sb;
        cpa_rm(s0, Ah, s0 + RM_BUF_HALVES * 2u, Al, H_, tid);
        cpa_rm(s0 + RM_BUF_HALVES * 4u, Bh, s0 + RM_BUF_HALVES * 6u, Bl, H_, tid);
        CP_COMMIT();
    }
    for (int k = 0; k < NK3; k++) {
        CP_WAIT0();
        __syncthreads();
        if (k + 1 < NK3) {
            unsigned s1 = sb + (unsigned)(((k + 1) & 1) * RM_STAGE_HALVES) * 2u;
            cpa_rm(s1, Ah + (k + 1) * 32, s1 + RM_BUF_HALVES * 2u, Al + (k + 1) * 32, H_, tid);
            cpa_rm(s1 + RM_BUF_HALVES * 4u, Bh + (k + 1) * 32,
                   s1 + RM_BUF_HALVES * 6u, Bl + (k + 1) * 32, H_, tid);
            CP_COMMIT();
        }
        unsigned s = sb + (unsigned)((k & 1) * RM_STAGE_HALVES) * 2u;
        mma_step_rm(s, s + RM_BUF_HALVES * 2u, s + RM_BUF_HALVES * 4u,
                    s + RM_BUF_HALVES * 6u, wm, wn, lane, acc);
    }
    epilogue(&g_Apart[(size_t)(p * B_ + b) * (T_ * T_)], T_, 1.f, wm, wn, lane, acc);
}

// ---------------------------------------------------------------------------
// K4: value-side scan, warp-autonomous, 4-way s-split.
//     grid (4,32): blockIdx.x = h-block (192 h), blockIdx.y = batch.
//     768 threads = 24 warps. Warp owns 8 h (lr=lane&7); q=lane>>3 is the
//     s-quarter. Partials combine via shfl_xor 8 + 16. Intra-block triangle
//     register-redundant across quarters. No __syncthreads in the main loop.
//     Dyn smem: A 64KB + vtr[128][192] 96KB = 160KB.
// ---------------------------------------------------------------------------
#define K4_BLK 16
#define K4H 192
#define K4T 768

__global__ __launch_bounds__(K4T) void k4_scan_val(float* __restrict__ out)
{
    extern __shared__ float sm4[];
    float* A_s   = sm4;            // [t][s] 128*128
    float* vtr_s = sm4 + 16384;    // [s][lh] 128*K4H

    const int hb   = blockIdx.x;
    const int b    = blockIdx.y;
    const int tid  = threadIdx.x;
    const int warp = tid >> 5;
    const int lane = tid & 31;
    const int lr   = lane & 7;
    const int q    = lane >> 3;          // s-quarter 0..3
    const int lh   = warp * 8 + lr;      // 0..191
    const int h    = hb * K4H + lh;

    // sum the 6 K-split partials of A into smem (768 threads), one sync
    {
        const float* ap = &g_Apart[(size_t)b * (T_ * T_)];
        for (int e = tid * 4; e < T_ * T_; e += K4T * 4) {
            float4 s = *(const float4*)&ap[e];
#pragma unroll
            for (int p = 1; p < 6; p++) {
                float4 v = *(const float4*)&ap[(size_t)p * B_ * T_ * T_ + e];
                s.x += v.x; s.y += v.y; s.z += v.z; s.w += v.w;
            }
            *(float4*)&A_s[e] = s;
        }
    }
    __syncthreads();

    const float* ivp = &g_i[b * T_ * H2_ + H_ + h];
    const int gbase = (b * T_) * H_ + h;
    float* valso = &out[OUT_VALS_ + gbase];

    float vv = 0.f, vtr = 0.f;

    for (int t0 = 0; t0 < T_; t0 += K4_BLK) {
        float iv_blk[K4_BLK];
#pragma unroll
        for (int j = 0; j < K4_BLK; j++) iv_blk[j] = ivp[(t0 + j) * H2_];

        // ---- cross phase: quarter q handles s in [q*t0/4, (q+1)*t0/4) ----
        const int qlen = t0 >> 2;            // multiple of 4
        const int sbeg = q * qlen;
        const int send = sbeg + qlen;

        float acc[K4_BLK];
#pragma unroll
        for (int j = 0; j < K4_BLK; j++) acc[j] = 0.f;

        for (int s4 = sbeg; s4 < send; s4 += 4) {
            float v0 = vtr_s[(s4 + 0) * K4H + lh];
            float v1 = vtr_s[(s4 + 1) * K4H + lh];
            float v2 = vtr_s[(s4 + 2) * K4H + lh];
            float v3 = vtr_s[(s4 + 3) * K4H + lh];
#pragma unroll
            for (int j = 0; j < K4_BLK; j++) {
                float4 a = *(const float4*)&A_s[(t0 + j) * T_ + s4];
                acc[j] = fmaf(a.x, v0, acc[j]);
                acc[j] = fmaf(a.y, v1, acc[j]);
                acc[j] = fmaf(a.z, v2, acc[j]);
                acc[j] = fmaf(a.w, v3, acc[j]);
            }
        }
        // combine quarters within the warp
#pragma unroll
        for (int j = 0; j < K4_BLK; j++) {
            acc[j] += __shfl_xor_sync(0xFFFFFFFFu, acc[j], 8);
            acc[j] += __shfl_xor_sync(0xFFFFFFFFu, acc[j], 16);
        }

        // ---- intra phase: register-resident, redundant across quarters ----
        float vtr_blk[K4_BLK];
#pragma unroll
        for (int j = 0; j < K4_BLK; j++) {
            const int t = t0 + j;
            float a = acc[j];
            const float* Arow = &A_s[t * T_ + t0];
#pragma unroll
            for (int sj = 0; sj < j; sj++)
                a = fmaf(Arow[sj], vtr_blk[sj], a);
            float ikv = CIKV_ * a;

            vv = ALPHA_ * vv + OMA_ * (iv_blk[j] + ikv);
            float val = tanh_fast(vv);
            vtr = DTR_ * vtr + OMD_ * val;
            vtr_blk[j] = vtr;
            if (q == 0) {
                valso[t * H_] = val;
                vtr_s[t * K4H + lh] = vtr;
                __nv_bfloat16 hh, ll;
                split_bf16(vtr, hh, ll);
                g_vtrh[gbase + t * H_] = hh;
                g_vtrl[gbase + t * H_] = ll;
            }
        }
        __syncwarp();   // vtr_s writes visible within the warp
    }
}

// ---------------------------------------------------------------------------
// K5: mem[b][i][j] = eta * sum_s vtr[b,s,i]*ktr[b,s,j]
//     k-major bf16 operands, trans-ldmatrix, cp.async double-buffered.
// ---------------------------------------------------------------------------
__global__ __launch_bounds__(256, 2) void k5_gemm_mem(float* __restrict__ out)
{
    extern __shared__ __nv_bfloat16 dyn[];
    const int b  = blockIdx.z;
    const int i0 = blockIdx.y * 128;
    const int j0 = blockIdx.x * 128;
    const int tid = threadIdx.x;
    const int warp = tid >> 5, lane = tid & 31;
    const int wm = warp >> 2, wn = warp & 3;

    unsigned sb = (unsigned)__cvta_generic_to_shared(dyn);

    const size_t bb = (size_t)b * T_ * H_;
    const __nv_bfloat16* Ah = &g_vtrh[bb + i0];
    const __nv_bfloat16* Al = &g_vtrl[bb + i0];
    const __nv_bfloat16* Bh = &g_ktrh[bb + j0];
    const __nv_bfloat16* Bl = &g_ktrl[bb + j0];

    float acc[4][4][4];
#pragma unroll
    for (int i = 0; i < 4; i++)
#pragma unroll
        for (int j = 0; j < 4; j++)
#pragma unroll
            for (int r = 0; r < 4; r++) acc[i][j][r] = 0.f;

#define NK5 4
    {
        unsigned s0 = sb;
        cpa_km(s0, Ah, s0 + KM_BUF_HALVES * 2u, Al, H_, tid);
        cpa_km(s0 + KM_BUF_HALVES * 4u, Bh, s0 + KM_BUF_HALVES * 6u, Bl, H_, tid);
        CP_COMMIT();
    }
    for (int k = 0; k < NK5; k++) {
        CP_WAIT0();
        __syncthreads();
        if (k + 1 < NK5) {
            unsigned s1 = sb + (unsigned)(((k + 1) & 1) * KM_STAGE_HALVES) * 2u;
            const size_t so = (size_t)(k + 1) * 32 * H_;
            cpa_km(s1, Ah + so, s1 + KM_BUF_HALVES * 2u, Al + so, H_, tid);
            cpa_km(s1 + KM_BUF_HALVES * 4u, Bh + so,
                   s1 + KM_BUF_HALVES * 6u, Bl + so, H_, tid);
            CP_COMMIT();
        }
        unsigned s = sb + (unsigned)((k & 1) * KM_STAGE_HALVES) * 2u;
        mma_step_km(s, s + KM_BUF_HALVES * 2u, s + KM_BUF_HALVES * 4u,
                    s + KM_BUF_HALVES * 6u, wm, wn, lane, acc);
    }
    epilogue(&out[(size_t)b * (H_ * H_) + (size_t)i0 * H_ + j0], H_, ETA_,
             wm, wn, lane, acc);
}

// ---------------------------------------------------------------------------
extern "C" void kernel_launch(void* const* d_in, const int* in_sizes, int n_in,
                              void* d_out, int out_size)
{
    const float* x = (const float*)d_in[0];   // (32,128,256)
    const float* W = (const float*)d_in[1];   // (1536,256)
    float* out = (float*)d_out;               // mem | keys | vals

    const int smem_rm = 2 * RM_STAGE_HALVES * 2;        // 81920
    const int smem_km = 2 * KM_STAGE_HALVES * 2;        // 69632
    const int smem_k4 = (16384 + 128 * K4H) * 4;        // 163840

    (void)cudaFuncSetAttribute(k1_gemm_in,
        cudaFuncAttributeMaxDynamicSharedMemorySize, smem_rm);
    (void)cudaFuncSetAttribute(k3_gemm_A,
        cudaFuncAttributeMaxDynamicSharedMemorySize, smem_rm);
    (void)cudaFuncSetAttribute(k5_gemm_mem,
        cudaFuncAttributeMaxDynamicSharedMemorySize, smem_km);
    (void)cudaFuncSetAttribute(k4_scan_val,
        cudaFuncAttributeMaxDynamicSharedMemorySize, smem_k4);

    k0_convert<<<(XN_ + WN_ + 1023) / 1024, 256>>>(x, W);
    k1_gemm_in<<<dim3(12, 32), 256, smem_rm>>>();
    k2_scan_key<<<96, 256>>>(out);
    k3_gemm_A<<<dim3(6, 32), 256, smem_rm>>>();
    k4_scan_val<<<dim3(4, 32), K4T, smem_k4>>>(out);
    k5_gemm_mem<<<dim3(6, 6, 32), 256, smem_km>>>(out);
}

// round 10
// speedup vs baseline: 1.1904x; 1.1904x over previous
#include <cuda_runtime.h>
#include <cuda_fp16.h>
#include <math.h>

// Problem constants
#define B_   32
#define T_   128
#define H_   768
#define IN_  256
#define H2_  1536

// exp(-1/20)
#define ALPHA_   0.951229424500714f
#define OMA_     0.048770575499286f
#define DTR_     0.951229424500714f
#define OMD_     0.048770575499286f
#define ETA_     0.1f
#define CIKV_    0.02f

// Output offsets (floats): mem | keys | vals
#define OUT_MEM_   0
#define OUT_KEYS_  18874368
#define OUT_VALS_  22020096

// Scratch (f32)
__device__ float g_i[B_ * T_ * H2_];
__device__ float g_Apart[6 * B_ * T_ * T_];

// fp16 operand arrays. A-side operands carry hi+lo; B-side hi only.
__device__ __half g_xh[B_ * T_ * IN_],  g_xl[B_ * T_ * IN_];
__device__ __half g_Wh[H2_ * IN_];
__device__ __half g_keyh[B_ * T_ * H_], g_keyl[B_ * T_ * H_];
__device__ __half g_ktrh[B_ * T_ * H_];
__device__ __half g_vtrh[B_ * T_ * H_], g_vtrl[B_ * T_ * H_];

__device__ __forceinline__ float tanh_fast(float x) {
    float y;
    asm("tanh.approx.f32 %0, %1;" : "=f"(y) : "f"(x));
    return y;
}
__device__ __forceinline__ void split_f16(float v, __half& hi, __half& lo) {
    hi = __float2half_rn(v);
    lo = __float2half_rn(v - __half2float(hi));
}

// ---------------------------------------------------------------------------
// mma.sync helpers (fp16, f32 accum)
// ---------------------------------------------------------------------------
__device__ __forceinline__ void ldsm_x4(unsigned addr, unsigned& r0, unsigned& r1,
                                        unsigned& r2, unsigned& r3) {
    asm volatile("ldmatrix.sync.aligned.m8n8.x4.shared.b16 {%0,%1,%2,%3}, [%4];"
                 : "=r"(r0), "=r"(r1), "=r"(r2), "=r"(r3) : "r"(addr));
}
__device__ __forceinline__ void ldsm_x4t(unsigned addr, unsigned& r0, unsigned& r1,
                                         unsigned& r2, unsigned& r3) {
    asm volatile("ldmatrix.sync.aligned.m8n8.x4.trans.shared.b16 {%0,%1,%2,%3}, [%4];"
                 : "=r"(r0), "=r"(r1), "=r"(r2), "=r"(r3) : "r"(addr));
}
__device__ __forceinline__ void mma16816(float* c, unsigned a0, unsigned a1,
                                         unsigned a2, unsigned a3,
                                         unsigned b0, unsigned b1) {
    asm volatile(
        "mma.sync.aligned.m16n8k16.row.col.f32.f16.f16.f32 "
        "{%0,%1,%2,%3}, {%4,%5,%6,%7}, {%8,%9}, {%0,%1,%2,%3};"
        : "+f"(c[0]), "+f"(c[1]), "+f"(c[2]), "+f"(c[3])
        : "r"(a0), "r"(a1), "r"(a2), "r"(a3), "r"(b0), "r"(b1));
}

// cp.async helpers
__device__ __forceinline__ void cp16(unsigned dst, const void* src) {
    asm volatile("cp.async.cg.shared.global [%0], [%1], 16;" :: "r"(dst), "l"(src));
}
#define CP_COMMIT() asm volatile("cp.async.commit_group;")
#define CP_WAIT0()  asm volatile("cp.async.wait_group 0;" ::: "memory")

#define SRM 40    // smem stride (halves) row-major tiles (128 rows x 32 k)
#define SKM 136   // smem stride (halves) k-major tiles (32 k x 128 m)
#define RM_BUF_HALVES (128 * SRM)            // 5120
#define RM_BUF_BYTES  (RM_BUF_HALVES * 2)    // 10240
#define RM_STAGE_BYTES (3 * RM_BUF_BYTES)    // Ah, Al, Bh
#define KM_BUF_HALVES (32 * SKM)             // 4352
#define KM_BUF_BYTES  (KM_BUF_HALVES * 2)    // 8704
#define KM_STAGE_BYTES (3 * KM_BUF_BYTES)

// Copy one row-major 128x32 fp16 tile into smem via cp.async.
__device__ __forceinline__ void cpa_rm1(unsigned dst, const __half* src,
                                        int ld, int tid)
{
#pragma unroll
    for (int l = 0; l < 2; l++) {
        int c = tid + l * 256;
        int row = c >> 2;
        int q   = c & 3;
        cp16(dst + (unsigned)(row * SRM * 2 + q * 16),
             (const char*)src + (size_t)row * ld * 2 + q * 16);
    }
}
// Copy one k-major 32x128 fp16 tile into smem.
__device__ __forceinline__ void cpa_km1(unsigned dst, const __half* src,
                                        int ld, int tid)
{
#pragma unroll
    for (int l = 0; l < 2; l++) {
        int c = tid + l * 256;
        int row = c >> 4;
        int q   = c & 15;
        cp16(dst + (unsigned)(row * SKM * 2 + q * 16),
             (const char*)src + (size_t)row * ld * 2 + q * 16);
    }
}

// One BK=32 compute step: row-major smem tiles, no-trans ldmatrix. 2 passes.
__device__ __forceinline__ void mma_step_rm(
    unsigned bAh, unsigned bAl, unsigned bBh,
    int wm, int wn, int lane, float acc[4][4][4])
{
    const int lr = lane & 15;
    const int kh = (lane >> 4) * 8;
#pragma unroll
    for (int ks = 0; ks < 32; ks += 16) {
        unsigned ah[4][4], al[4][4], bh[4][2];
#pragma unroll
        for (int i = 0; i < 4; i++) {
            unsigned off = 2u * ((wm * 64 + i * 16 + lr) * SRM + ks + kh);
            ldsm_x4(bAh + off, ah[i][0], ah[i][1], ah[i][2], ah[i][3]);
            ldsm_x4(bAl + off, al[i][0], al[i][1], al[i][2], al[i][3]);
        }
#pragma unroll
        for (int p = 0; p < 2; p++) {
            unsigned off = 2u * ((wn * 32 + p * 16 + lr) * SRM + ks + kh);
            unsigned r0, r1, r2, r3;
            ldsm_x4(bBh + off, r0, r1, r2, r3);
            bh[p * 2 + 0][0] = r0; bh[p * 2 + 0][1] = r2;
            bh[p * 2 + 1][0] = r1; bh[p * 2 + 1][1] = r3;
        }
#pragma unroll
        for (int i = 0; i < 4; i++)
#pragma unroll
            for (int j = 0; j < 4; j++) {
                mma16816(acc[i][j], ah[i][0], ah[i][1], ah[i][2], ah[i][3],
                         bh[j][0], bh[j][1]);
                mma16816(acc[i][j], al[i][0], al[i][1], al[i][2], al[i][3],
                         bh[j][0], bh[j][1]);
            }
    }
}

// One BK=32 compute step: k-major smem tiles, trans ldmatrix. 2 passes.
__device__ __forceinline__ void mma_step_km(
    unsigned bAh, unsigned bAl, unsigned bBh,
    int wm, int wn, int lane, float acc[4][4][4])
{
    const int krow = (lane & 7) + ((lane >> 4) << 3);
    const int mcol = ((lane >> 3) & 1) * 8;
#pragma unroll
    for (int ks = 0; ks < 32; ks += 16) {
        unsigned ah[4][4], al[4][4], bh[4][2];
#pragma unroll
        for (int i = 0; i < 4; i++) {
            unsigned off = 2u * ((ks + krow) * SKM + wm * 64 + i * 16 + mcol);
            ldsm_x4t(bAh + off, ah[i][0], ah[i][1], ah[i][2], ah[i][3]);
            ldsm_x4t(bAl + off, al[i][0], al[i][1], al[i][2], al[i][3]);
        }
#pragma unroll
        for (int p = 0; p < 2; p++) {
            unsigned off = 2u * ((ks + krow) * SKM + wn * 32 + p * 16 + mcol);
            unsigned r0, r1, r2, r3;
            ldsm_x4t(bBh + off, r0, r1, r2, r3);
            bh[p * 2 + 0][0] = r0; bh[p * 2 + 0][1] = r2;
            bh[p * 2 + 1][0] = r1; bh[p * 2 + 1][1] = r3;
        }
#pragma unroll
        for (int i = 0; i < 4; i++)
#pragma unroll
            for (int j = 0; j < 4; j++) {
                mma16816(acc[i][j], ah[i][0], ah[i][1], ah[i][2], ah[i][3],
                         bh[j][0], bh[j][1]);
                mma16816(acc[i][j], al[i][0], al[i][1], al[i][2], al[i][3],
                         bh[j][0], bh[j][1]);
            }
    }
}

// Epilogue: write 4x4 m16n8 tiles to gmem, scaled.
__device__ __forceinline__ void epilogue(float* dst, int ldc, float scale,
                                         int wm, int wn, int lane,
                                         float acc[4][4][4])
{
    const int r0 = lane >> 2;
    const int c0 = (lane & 3) * 2;
#pragma unroll
    for (int i = 0; i < 4; i++)
#pragma unroll
        for (int j = 0; j < 4; j++) {
            int row = wm * 64 + i * 16 + r0;
            int col = wn * 32 + j * 8 + c0;
            float2 v0 = make_float2(scale * acc[i][j][0], scale * acc[i][j][1]);
            float2 v1 = make_float2(scale * acc[i][j][2], scale * acc[i][j][3]);
            *(float2*)&dst[row * ldc + col] = v0;
            *(float2*)&dst[(row + 8) * ldc + col] = v1;
        }
}

// ---------------------------------------------------------------------------
// K0: pre-split x (hi+lo) and W (hi only) to fp16
// ---------------------------------------------------------------------------
#define XN_ (B_ * T_ * IN_)   // 1048576
#define WN_ (H2_ * IN_)       // 393216

__global__ __launch_bounds__(256) void k0_convert(
    const float* __restrict__ x, const float* __restrict__ W)
{
    int i4 = (blockIdx.x * 256 + threadIdx.x) * 4;
    if (i4 < XN_) {
        float4 v = *(const float4*)&x[i4];
        __half h0, l0, h1, l1, h2, l2, h3, l3;
        split_f16(v.x, h0, l0); split_f16(v.y, h1, l1);
        split_f16(v.z, h2, l2); split_f16(v.w, h3, l3);
        g_xh[i4 + 0] = h0; g_xh[i4 + 1] = h1; g_xh[i4 + 2] = h2; g_xh[i4 + 3] = h3;
        g_xl[i4 + 0] = l0; g_xl[i4 + 1] = l1; g_xl[i4 + 2] = l2; g_xl[i4 + 3] = l3;
    } else if (i4 < XN_ + WN_) {
        int off = i4 - XN_;
        float4 v = *(const float4*)&W[off];
        g_Wh[off + 0] = __float2half_rn(v.x);
        g_Wh[off + 1] = __float2half_rn(v.y);
        g_Wh[off + 2] = __float2half_rn(v.z);
        g_Wh[off + 3] = __float2half_rn(v.w);
    }
}

// ---------------------------------------------------------------------------
// K1: g_i[m][n] = sum_k x[m][k]*W[n][k]   M=4096 N=1536 K=256 (NK=8)
//     cp.async double-buffered, 3 tiles/stage. Dyn smem 2*30720 = 61440B.
// ---------------------------------------------------------------------------
__global__ __launch_bounds__(256, 2) void k1_gemm_in()
{
    extern __shared__ __half dyn[];
    const int m0 = blockIdx.y * 128;
    const int n0 = blockIdx.x * 128;
    const int tid = threadIdx.x;
    const int warp = tid >> 5, lane = tid & 31;
    const int wm = warp >> 2, wn = warp & 3;

    unsigned sb = (unsigned)__cvta_generic_to_shared(dyn);

    float acc[4][4][4];
#pragma unroll
    for (int i = 0; i < 4; i++)
#pragma unroll
        for (int j = 0; j < 4; j++)
#pragma unroll
            for (int r = 0; r < 4; r++) acc[i][j][r] = 0.f;

    const __half* Ah = &g_xh[(size_t)m0 * IN_];
    const __half* Al = &g_xl[(size_t)m0 * IN_];
    const __half* Bh = &g_Wh[(size_t)n0 * IN_];

#define NK1 8
    {
        cpa_rm1(sb,                    Ah, IN_, tid);
        cpa_rm1(sb + RM_BUF_BYTES,     Al, IN_, tid);
        cpa_rm1(sb + 2 * RM_BUF_BYTES, Bh, IN_, tid);
        CP_COMMIT();
    }
    for (int k = 0; k < NK1; k++) {
        CP_WAIT0();
        __syncthreads();
        if (k + 1 < NK1) {
            unsigned s1 = sb + (unsigned)(((k + 1) & 1) * RM_STAGE_BYTES);
            cpa_rm1(s1,                    Ah + (k + 1) * 32, IN_, tid);
            cpa_rm1(s1 + RM_BUF_BYTES,     Al + (k + 1) * 32, IN_, tid);
            cpa_rm1(s1 + 2 * RM_BUF_BYTES, Bh + (k + 1) * 32, IN_, tid);
            CP_COMMIT();
        }
        unsigned s = sb + (unsigned)((k & 1) * RM_STAGE_BYTES);
        mma_step_rm(s, s + RM_BUF_BYTES, s + 2 * RM_BUF_BYTES, wm, wn, lane, acc);
    }
    epilogue(&g_i[(size_t)m0 * H2_ + n0], H2_, 1.f, wm, wn, lane, acc);
}

// ---------------------------------------------------------------------------
// K2: key-side elementwise scan; writes keys f32, key hi/lo, ktr hi (fp16)
// ---------------------------------------------------------------------------
__global__ __launch_bounds__(256) void k2_scan_key(float* __restrict__ out)
{
    const int b  = blockIdx.x / 3;
    const int h  = (blockIdx.x % 3) * 256 + threadIdx.x;

    const float* ik = &g_i[(b * T_) * H2_ + h];
    const int base = (b * T_) * H_ + h;
    float* keyso = &out[OUT_KEYS_ + base];

    float kv = 0.f, ktr = 0.f;
#pragma unroll 4
    for (int t = 0; t < T_; t++) {
        kv = ALPHA_ * kv + OMA_ * ik[t * H2_];
        float key = tanh_fast(kv);
        ktr = DTR_ * ktr + OMD_ * key;
        keyso[t * H_] = key;
        __half hh, ll;
        split_f16(key, hh, ll);
        g_keyh[base + t * H_] = hh;
        g_keyl[base + t * H_] = ll;
        g_ktrh[base + t * H_] = __float2half_rn(ktr);
    }
}

// ---------------------------------------------------------------------------
// K3: Apart[p][b][t][s] = sum_{k in chunk p} key[b,t,k]*ktr[b,s,k]
//     grid (6,32). NK=4.
// ---------------------------------------------------------------------------
__global__ __launch_bounds__(256, 2) void k3_gemm_A()
{
    extern __shared__ __half dyn[];
    const int p = blockIdx.x;
    const int b = blockIdx.y;
    const int tid = threadIdx.x;
    const int warp = tid >> 5, lane = tid & 31;
    const int wm = warp >> 2, wn = warp & 3;

    unsigned sb = (unsigned)__cvta_generic_to_shared(dyn);

    const size_t base = (size_t)b * T_ * H_ + p * 128;
    const __half* Ah = &g_keyh[base];
    const __half* Al = &g_keyl[base];
    const __half* Bh = &g_ktrh[base];

    float acc[4][4][4];
#pragma unroll
    for (int i = 0; i < 4; i++)
#pragma unroll
        for (int j = 0; j < 4; j++)
#pragma unroll
            for (int r = 0; r < 4; r++) acc[i][j][r] = 0.f;

#define NK3 4
    {
        cpa_rm1(sb,                    Ah, H_, tid);
        cpa_rm1(sb + RM_BUF_BYTES,     Al, H_, tid);
        cpa_rm1(sb + 2 * RM_BUF_BYTES, Bh, H_, tid);
        CP_COMMIT();
    }
    for (int k = 0; k < NK3; k++) {
        CP_WAIT0();
        __syncthreads();
        if (k + 1 < NK3) {
            unsigned s1 = sb + (unsigned)(((k + 1) & 1) * RM_STAGE_BYTES);
            cpa_rm1(s1,                    Ah + (k + 1) * 32, H_, tid);
            cpa_rm1(s1 + RM_BUF_BYTES,     Al + (k + 1) * 32, H_, tid);
            cpa_rm1(s1 + 2 * RM_BUF_BYTES, Bh + (k + 1) * 32, H_, tid);
            CP_COMMIT();
        }
        unsigned s = sb + (unsigned)((k & 1) * RM_STAGE_BYTES);
        mma_step_rm(s, s + RM_BUF_BYTES, s + 2 * RM_BUF_BYTES, wm, wn, lane, acc);
    }
    epilogue(&g_Apart[(size_t)(p * B_ + b) * (T_ * T_)], T_, 1.f, wm, wn, lane, acc);
}

// ---------------------------------------------------------------------------
// K4: value-side scan, warp-autonomous 2-way split (proven R6 core).
//     512 threads = 16 warps; lr = lane&15 picks h, half = lane>>4 splits s.
//     Writes vals f32 + vtr hi/lo fp16.
// ---------------------------------------------------------------------------
#define K4_BLK 16

__global__ __launch_bounds__(512) void k4_scan_val(float* __restrict__ out)
{
    extern __shared__ float sm4[];
    float* A_s   = sm4;            // [t][s] 128*128
    float* vtr_s = sm4 + 16384;    // [s][lh] 128*256

    const int b    = blockIdx.x / 3;
    const int hb   = blockIdx.x % 3;
    const int tid  = threadIdx.x;
    const int warp = tid >> 5;
    const int lane = tid & 31;
    const int lr   = lane & 15;
    const int half = lane >> 4;
    const int lh   = warp * 16 + lr;
    const int h    = hb * 256 + lh;

    {
        const float* ap = &g_Apart[(size_t)b * (T_ * T_)];
        for (int e = tid * 4; e < T_ * T_; e += 512 * 4) {
            float4 s = *(const float4*)&ap[e];
#pragma unroll
            for (int p = 1; p < 6; p++) {
                float4 v = *(const float4*)&ap[(size_t)p * B_ * T_ * T_ + e];
                s.x += v.x; s.y += v.y; s.z += v.z; s.w += v.w;
            }
            *(float4*)&A_s[e] = s;
        }
    }
    __syncthreads();

    const float* ivp = &g_i[b * T_ * H2_ + H_ + h];
    const int gbase = (b * T_) * H_ + h;
    float* valso = &out[OUT_VALS_ + gbase];

    float vv = 0.f, vtr = 0.f;

    for (int t0 = 0; t0 < T_; t0 += K4_BLK) {
        float iv_blk[K4_BLK];
#pragma unroll
        for (int j = 0; j < K4_BLK; j++) iv_blk[j] = ivp[(t0 + j) * H2_];

        const int mid  = t0 >> 1;
        const int sbeg = half ? mid : 0;
        const int send = half ? t0  : mid;

        float acc[K4_BLK];
#pragma unroll
        for (int j = 0; j < K4_BLK; j++) acc[j] = 0.f;

        for (int s4 = sbeg; s4 < send; s4 += 4) {
            float v0 = vtr_s[(s4 + 0) * 256 + lh];
            float v1 = vtr_s[(s4 + 1) * 256 + lh];
            float v2 = vtr_s[(s4 + 2) * 256 + lh];
            float v3 = vtr_s[(s4 + 3) * 256 + lh];
#pragma unroll
            for (int j = 0; j < K4_BLK; j++) {
                float4 a = *(const float4*)&A_s[(t0 + j) * T_ + s4];
                acc[j] = fmaf(a.x, v0, acc[j]);
                acc[j] = fmaf(a.y, v1, acc[j]);
                acc[j] = fmaf(a.z, v2, acc[j]);
                acc[j] = fmaf(a.w, v3, acc[j]);
            }
        }
#pragma unroll
        for (int j = 0; j < K4_BLK; j++)
            acc[j] += __shfl_xor_sync(0xFFFFFFFFu, acc[j], 16);

        float vtr_blk[K4_BLK];
#pragma unroll
        for (int j = 0; j < K4_BLK; j++) {
            const int t = t0 + j;
            float a = acc[j];
            const float* Arow = &A_s[t * T_ + t0];
#pragma unroll
            for (int sj = 0; sj < j; sj++)
                a = fmaf(Arow[sj], vtr_blk[sj], a);
            float ikv = CIKV_ * a;

            vv = ALPHA_ * vv + OMA_ * (iv_blk[j] + ikv);
            float val = tanh_fast(vv);
            vtr = DTR_ * vtr + OMD_ * val;
            vtr_blk[j] = vtr;
            if (!half) {
                valso[t * H_] = val;
                vtr_s[t * 256 + lh] = vtr;
                __half hh, ll;
                split_f16(vtr, hh, ll);
                g_vtrh[gbase + t * H_] = hh;
                g_vtrl[gbase + t * H_] = ll;
            }
        }
        __syncwarp();
    }
}

// ---------------------------------------------------------------------------
// K5: mem[b][i][j] = eta * sum_s vtr[b,s,i]*ktr[b,s,j]
//     k-major fp16 operands (A = vtr hi/lo, B = ktr hi), trans-ldmatrix.
//     grid (6,6,32), NK=4. Dyn smem 2*26112 = 52224B.
// ---------------------------------------------------------------------------
__global__ __launch_bounds__(256, 2) void k5_gemm_mem(float* __restrict__ out)
{
    extern __shared__ __half dyn[];
    const int b  = blockIdx.z;
    const int i0 = blockIdx.y * 128;
    const int j0 = blockIdx.x * 128;
    const int tid = threadIdx.x;
    const int warp = tid >> 5, lane = tid & 31;
    const int wm = warp >> 2, wn = warp & 3;

    unsigned sb = (unsigned)__cvta_generic_to_shared(dyn);

    const size_t bb = (size_t)b * T_ * H_;
    const __half* Ah = &g_vtrh[bb + i0];
    const __half* Al = &g_vtrl[bb + i0];
    const __half* Bh = &g_ktrh[bb + j0];

    float acc[4][4][4];
#pragma unroll
    for (int i = 0; i < 4; i++)
#pragma unroll
        for (int j = 0; j < 4; j++)
#pragma unroll
            for (int r = 0; r < 4; r++) acc[i][j][r] = 0.f;

#define NK5 4
    {
        cpa_km1(sb,                    Ah, H_, tid);
        cpa_km1(sb + KM_BUF_BYTES,     Al, H_, tid);
        cpa_km1(sb + 2 * KM_BUF_BYTES, Bh, H_, tid);
        CP_COMMIT();
    }
    for (int k = 0; k < NK5; k++) {
        CP_WAIT0();
        __syncthreads();
        if (k + 1 < NK5) {
            unsigned s1 = sb + (unsigned)(((k + 1) & 1) * KM_STAGE_BYTES);
            const size_t so = (size_t)(k + 1) * 32 * H_;
            cpa_km1(s1,                    Ah + so, H_, tid);
            cpa_km1(s1 + KM_BUF_BYTES,     Al + so, H_, tid);
            cpa_km1(s1 + 2 * KM_BUF_BYTES, Bh + so, H_, tid);
            CP_COMMIT();
        }
        unsigned s = sb + (unsigned)((k & 1) * KM_STAGE_BYTES);
        mma_step_km(s, s + KM_BUF_BYTES, s + 2 * KM_BUF_BYTES, wm, wn, lane, acc);
    }
    epilogue(&out[(size_t)b * (H_ * H_) + (size_t)i0 * H_ + j0], H_, ETA_,
             wm, wn, lane, acc);
}

// ---------------------------------------------------------------------------
extern "C" void kernel_launch(void* const* d_in, const int* in_sizes, int n_in,
                              void* d_out, int out_size)
{
    const float* x = (const float*)d_in[0];   // (32,128,256)
    const float* W = (const float*)d_in[1];   // (1536,256)
    float* out = (float*)d_out;               // mem | keys | vals

    const int smem_rm = 2 * RM_STAGE_BYTES;       // 61440
    const int smem_km = 2 * KM_STAGE_BYTES;       // 52224
    const int smem_k4 = (16384 + 32768) * 4;      // 196608

    (void)cudaFuncSetAttribute(k1_gemm_in,
        cudaFuncAttributeMaxDynamicSharedMemorySize, smem_rm);
    (void)cudaFuncSetAttribute(k3_gemm_A,
        cudaFuncAttributeMaxDynamicSharedMemorySize, smem_rm);
    (void)cudaFuncSetAttribute(k5_gemm_mem,
        cudaFuncAttributeMaxDynamicSharedMemorySize, smem_km);
    (void)cudaFuncSetAttribute(k4_scan_val,
        cudaFuncAttributeMaxDynamicSharedMemorySize, smem_k4);

    k0_convert<<<(XN_ + WN_ + 1023) / 1024, 256>>>(x, W);
    k1_gemm_in<<<dim3(12, 32), 256, smem_rm>>>();
    k2_scan_key<<<96, 256>>>(out);
    k3_gemm_A<<<dim3(6, 32), 256, smem_rm>>>();
    k4_scan_val<<<96, 512, smem_k4>>>(out);
    k5_gemm_mem<<<dim3(6, 6, 32), 256, smem_km>>>(out);
}

// round 11
// speedup vs baseline: 1.3344x; 1.1210x over previous
#include <cuda_runtime.h>
#include <cuda_fp16.h>
#include <math.h>

// Problem constants
#define B_   32
#define T_   128
#define H_   768
#define IN_  256
#define H2_  1536

// exp(-1/20)
#define ALPHA_   0.951229424500714f
#define OMA_     0.048770575499286f
#define DTR_     0.951229424500714f
#define OMD_     0.048770575499286f
#define ETA_     0.1f
#define CIKV_    0.02f

// Output offsets (floats): mem | keys | vals
#define OUT_MEM_   0
#define OUT_KEYS_  18874368
#define OUT_VALS_  22020096

// Scratch (f32)
__device__ float g_i[B_ * T_ * H2_];
__device__ float g_Apart[6 * B_ * T_ * T_];

// fp16 operand arrays. x carries hi+lo (K1 2-pass); all others hi only.
__device__ __half g_xh[B_ * T_ * IN_],  g_xl[B_ * T_ * IN_];
__device__ __half g_Wh[H2_ * IN_];
__device__ __half g_keyh[B_ * T_ * H_];
__device__ __half g_ktrh[B_ * T_ * H_];
__device__ __half g_vtrh[B_ * T_ * H_];

__device__ __forceinline__ float tanh_fast(float x) {
    float y;
    asm("tanh.approx.f32 %0, %1;" : "=f"(y) : "f"(x));
    return y;
}
__device__ __forceinline__ void split_f16(float v, __half& hi, __half& lo) {
    hi = __float2half_rn(v);
    lo = __float2half_rn(v - __half2float(hi));
}

// ---------------------------------------------------------------------------
// mma.sync helpers (fp16, f32 accum)
// ---------------------------------------------------------------------------
__device__ __forceinline__ void ldsm_x4(unsigned addr, unsigned& r0, unsigned& r1,
                                        unsigned& r2, unsigned& r3) {
    asm volatile("ldmatrix.sync.aligned.m8n8.x4.shared.b16 {%0,%1,%2,%3}, [%4];"
                 : "=r"(r0), "=r"(r1), "=r"(r2), "=r"(r3) : "r"(addr));
}
__device__ __forceinline__ void ldsm_x4t(unsigned addr, unsigned& r0, unsigned& r1,
                                         unsigned& r2, unsigned& r3) {
    asm volatile("ldmatrix.sync.aligned.m8n8.x4.trans.shared.b16 {%0,%1,%2,%3}, [%4];"
                 : "=r"(r0), "=r"(r1), "=r"(r2), "=r"(r3) : "r"(addr));
}
__device__ __forceinline__ void mma16816(float* c, unsigned a0, unsigned a1,
                                         unsigned a2, unsigned a3,
                                         unsigned b0, unsigned b1) {
    asm volatile(
        "mma.sync.aligned.m16n8k16.row.col.f32.f16.f16.f32 "
        "{%0,%1,%2,%3}, {%4,%5,%6,%7}, {%8,%9}, {%0,%1,%2,%3};"
        : "+f"(c[0]), "+f"(c[1]), "+f"(c[2]), "+f"(c[3])
        : "r"(a0), "r"(a1), "r"(a2), "r"(a3), "r"(b0), "r"(b1));
}

// cp.async helpers
__device__ __forceinline__ void cp16(unsigned dst, const void* src) {
    asm volatile("cp.async.cg.shared.global [%0], [%1], 16;" :: "r"(dst), "l"(src));
}
#define CP_COMMIT() asm volatile("cp.async.commit_group;")
#define CP_WAIT0()  asm volatile("cp.async.wait_group 0;" ::: "memory")

#define SRM 40    // smem stride (halves) row-major tiles (128 rows x 32 k)
#define SKM 136   // smem stride (halves) k-major tiles (32 k x 128 m)
#define RM_BUF_HALVES (128 * SRM)            // 5120
#define RM_BUF_BYTES  (RM_BUF_HALVES * 2)    // 10240
#define RM_STAGE3_BYTES (3 * RM_BUF_BYTES)   // K1: Ah, Al, Bh
#define RM_STAGE2_BYTES (2 * RM_BUF_BYTES)   // K3: Ah, Bh
#define KM_BUF_HALVES (32 * SKM)             // 4352
#define KM_BUF_BYTES  (KM_BUF_HALVES * 2)    // 8704
#define KM_STAGE2_BYTES (2 * KM_BUF_BYTES)   // K5: Ah, Bh

// Copy one row-major 128x32 fp16 tile into smem via cp.async.
__device__ __forceinline__ void cpa_rm1(unsigned dst, const __half* src,
                                        int ld, int tid)
{
#pragma unroll
    for (int l = 0; l < 2; l++) {
        int c = tid + l * 256;
        int row = c >> 2;
        int q   = c & 3;
        cp16(dst + (unsigned)(row * SRM * 2 + q * 16),
             (const char*)src + (size_t)row * ld * 2 + q * 16);
    }
}
// Copy one k-major 32x128 fp16 tile into smem.
__device__ __forceinline__ void cpa_km1(unsigned dst, const __half* src,
                                        int ld, int tid)
{
#pragma unroll
    for (int l = 0; l < 2; l++) {
        int c = tid + l * 256;
        int row = c >> 4;
        int q   = c & 15;
        cp16(dst + (unsigned)(row * SKM * 2 + q * 16),
             (const char*)src + (size_t)row * ld * 2 + q * 16);
    }
}

// BK=32 compute step, row-major tiles, 2 A-passes (K1).
__device__ __forceinline__ void mma_step_rm2(
    unsigned bAh, unsigned bAl, unsigned bBh,
    int wm, int wn, int lane, float acc[4][4][4])
{
    const int lr = lane & 15;
    const int kh = (lane >> 4) * 8;
#pragma unroll
    for (int ks = 0; ks < 32; ks += 16) {
        unsigned ah[4][4], al[4][4], bh[4][2];
#pragma unroll
        for (int i = 0; i < 4; i++) {
            unsigned off = 2u * ((wm * 64 + i * 16 + lr) * SRM + ks + kh);
            ldsm_x4(bAh + off, ah[i][0], ah[i][1], ah[i][2], ah[i][3]);
            ldsm_x4(bAl + off, al[i][0], al[i][1], al[i][2], al[i][3]);
        }
#pragma unroll
        for (int p = 0; p < 2; p++) {
            unsigned off = 2u * ((wn * 32 + p * 16 + lr) * SRM + ks + kh);
            unsigned r0, r1, r2, r3;
            ldsm_x4(bBh + off, r0, r1, r2, r3);
            bh[p * 2 + 0][0] = r0; bh[p * 2 + 0][1] = r2;
            bh[p * 2 + 1][0] = r1; bh[p * 2 + 1][1] = r3;
        }
#pragma unroll
        for (int i = 0; i < 4; i++)
#pragma unroll
            for (int j = 0; j < 4; j++) {
                mma16816(acc[i][j], ah[i][0], ah[i][1], ah[i][2], ah[i][3],
                         bh[j][0], bh[j][1]);
                mma16816(acc[i][j], al[i][0], al[i][1], al[i][2], al[i][3],
                         bh[j][0], bh[j][1]);
            }
    }
}

// BK=32 compute step, row-major tiles, single pass (K3).
__device__ __forceinline__ void mma_step_rm1(
    unsigned bAh, unsigned bBh,
    int wm, int wn, int lane, float acc[4][4][4])
{
    const int lr = lane & 15;
    const int kh = (lane >> 4) * 8;
#pragma unroll
    for (int ks = 0; ks < 32; ks += 16) {
        unsigned ah[4][4], bh[4][2];
#pragma unroll
        for (int i = 0; i < 4; i++) {
            unsigned off = 2u * ((wm * 64 + i * 16 + lr) * SRM + ks + kh);
            ldsm_x4(bAh + off, ah[i][0], ah[i][1], ah[i][2], ah[i][3]);
        }
#pragma unroll
        for (int p = 0; p < 2; p++) {
            unsigned off = 2u * ((wn * 32 + p * 16 + lr) * SRM + ks + kh);
            unsigned r0, r1, r2, r3;
            ldsm_x4(bBh + off, r0, r1, r2, r3);
            bh[p * 2 + 0][0] = r0; bh[p * 2 + 0][1] = r2;
            bh[p * 2 + 1][0] = r1; bh[p * 2 + 1][1] = r3;
        }
#pragma unroll
        for (int i = 0; i < 4; i++)
#pragma unroll
            for (int j = 0; j < 4; j++)
                mma16816(acc[i][j], ah[i][0], ah[i][1], ah[i][2], ah[i][3],
                         bh[j][0], bh[j][1]);
    }
}

// BK=32 compute step, k-major tiles, single pass (K5).
__device__ __forceinline__ void mma_step_km1(
    unsigned bAh, unsigned bBh,
    int wm, int wn, int lane, float acc[4][4][4])
{
    const int krow = (lane & 7) + ((lane >> 4) << 3);
    const int mcol = ((lane >> 3) & 1) * 8;
#pragma unroll
    for (int ks = 0; ks < 32; ks += 16) {
        unsigned ah[4][4], bh[4][2];
#pragma unroll
        for (int i = 0; i < 4; i++) {
            unsigned off = 2u * ((ks + krow) * SKM + wm * 64 + i * 16 + mcol);
            ldsm_x4t(bAh + off, ah[i][0], ah[i][1], ah[i][2], ah[i][3]);
        }
#pragma unroll
        for (int p = 0; p < 2; p++) {
            unsigned off = 2u * ((ks + krow) * SKM + wn * 32 + p * 16 + mcol);
            unsigned r0, r1, r2, r3;
            ldsm_x4t(bBh + off, r0, r1, r2, r3);
            bh[p * 2 + 0][0] = r0; bh[p * 2 + 0][1] = r2;
            bh[p * 2 + 1][0] = r1; bh[p * 2 + 1][1] = r3;
        }
#pragma unroll
        for (int i = 0; i < 4; i++)
#pragma unroll
            for (int j = 0; j < 4; j++)
                mma16816(acc[i][j], ah[i][0], ah[i][1], ah[i][2], ah[i][3],
                         bh[j][0], bh[j][1]);
    }
}

// Epilogue: write 4x4 m16n8 tiles to gmem, scaled.
__device__ __forceinline__ void epilogue(float* dst, int ldc, float scale,
                                         int wm, int wn, int lane,
                                         float acc[4][4][4])
{
    const int r0 = lane >> 2;
    const int c0 = (lane & 3) * 2;
#pragma unroll
    for (int i = 0; i < 4; i++)
#pragma unroll
        for (int j = 0; j < 4; j++) {
            int row = wm * 64 + i * 16 + r0;
            int col = wn * 32 + j * 8 + c0;
            float2 v0 = make_float2(scale * acc[i][j][0], scale * acc[i][j][1]);
            float2 v1 = make_float2(scale * acc[i][j][2], scale * acc[i][j][3]);
            *(float2*)&dst[row * ldc + col] = v0;
            *(float2*)&dst[(row + 8) * ldc + col] = v1;
        }
}

// ---------------------------------------------------------------------------
// K0: pre-split x (hi+lo) and W (hi only) to fp16
// ---------------------------------------------------------------------------
#define XN_ (B_ * T_ * IN_)   // 1048576
#define WN_ (H2_ * IN_)       // 393216

__global__ __launch_bounds__(256) void k0_convert(
    const float* __restrict__ x, const float* __restrict__ W)
{
    int i4 = (blockIdx.x * 256 + threadIdx.x) * 4;
    if (i4 < XN_) {
        float4 v = *(const float4*)&x[i4];
        __half h0, l0, h1, l1, h2, l2, h3, l3;
        split_f16(v.x, h0, l0); split_f16(v.y, h1, l1);
        split_f16(v.z, h2, l2); split_f16(v.w, h3, l3);
        g_xh[i4 + 0] = h0; g_xh[i4 + 1] = h1; g_xh[i4 + 2] = h2; g_xh[i4 + 3] = h3;
        g_xl[i4 + 0] = l0; g_xl[i4 + 1] = l1; g_xl[i4 + 2] = l2; g_xl[i4 + 3] = l3;
    } else if (i4 < XN_ + WN_) {
        int off = i4 - XN_;
        float4 v = *(const float4*)&W[off];
        g_Wh[off + 0] = __float2half_rn(v.x);
        g_Wh[off + 1] = __float2half_rn(v.y);
        g_Wh[off + 2] = __float2half_rn(v.z);
        g_Wh[off + 3] = __float2half_rn(v.w);
    }
}

// ---------------------------------------------------------------------------
// K1: g_i[m][n] = sum_k x[m][k]*W[n][k]   M=4096 N=1536 K=256 (NK=8)
//     2-pass (x hi/lo), cp.async double-buffered. Dyn smem 61440B.
// ---------------------------------------------------------------------------
__global__ __launch_bounds__(256, 2) void k1_gemm_in()
{
    extern __shared__ __half dyn[];
    const int m0 = blockIdx.y * 128;
    const int n0 = blockIdx.x * 128;
    const int tid = threadIdx.x;
    const int warp = tid >> 5, lane = tid & 31;
    const int wm = warp >> 2, wn = warp & 3;

    unsigned sb = (unsigned)__cvta_generic_to_shared(dyn);

    float acc[4][4][4];
#pragma unroll
    for (int i = 0; i < 4; i++)
#pragma unroll
        for (int j = 0; j < 4; j++)
#pragma unroll
            for (int r = 0; r < 4; r++) acc[i][j][r] = 0.f;

    const __half* Ah = &g_xh[(size_t)m0 * IN_];
    const __half* Al = &g_xl[(size_t)m0 * IN_];
    const __half* Bh = &g_Wh[(size_t)n0 * IN_];

#define NK1 8
    {
        cpa_rm1(sb,                    Ah, IN_, tid);
        cpa_rm1(sb + RM_BUF_BYTES,     Al, IN_, tid);
        cpa_rm1(sb + 2 * RM_BUF_BYTES, Bh, IN_, tid);
        CP_COMMIT();
    }
    for (int k = 0; k < NK1; k++) {
        CP_WAIT0();
        __syncthreads();
        if (k + 1 < NK1) {
            unsigned s1 = sb + (unsigned)(((k + 1) & 1) * RM_STAGE3_BYTES);
            cpa_rm1(s1,                    Ah + (k + 1) * 32, IN_, tid);
            cpa_rm1(s1 + RM_BUF_BYTES,     Al + (k + 1) * 32, IN_, tid);
            cpa_rm1(s1 + 2 * RM_BUF_BYTES, Bh + (k + 1) * 32, IN_, tid);
            CP_COMMIT();
        }
        unsigned s = sb + (unsigned)((k & 1) * RM_STAGE3_BYTES);
        mma_step_rm2(s, s + RM_BUF_BYTES, s + 2 * RM_BUF_BYTES, wm, wn, lane, acc);
    }
    epilogue(&g_i[(size_t)m0 * H2_ + n0], H2_, 1.f, wm, wn, lane, acc);
}

// ---------------------------------------------------------------------------
// K2: key-side elementwise scan; writes keys f32, key hi, ktr hi (fp16)
// ---------------------------------------------------------------------------
__global__ __launch_bounds__(256) void k2_scan_key(float* __restrict__ out)
{
    const int b  = blockIdx.x / 3;
    const int h  = (blockIdx.x % 3) * 256 + threadIdx.x;

    const float* ik = &g_i[(b * T_) * H2_ + h];
    const int base = (b * T_) * H_ + h;
    float* keyso = &out[OUT_KEYS_ + base];

    float kv = 0.f, ktr = 0.f;
#pragma unroll 4
    for (int t = 0; t < T_; t++) {
        kv = ALPHA_ * kv + OMA_ * ik[t * H2_];
        float key = tanh_fast(kv);
        ktr = DTR_ * ktr + OMD_ * key;
        keyso[t * H_] = key;
        g_keyh[base + t * H_] = __float2half_rn(key);
        g_ktrh[base + t * H_] = __float2half_rn(ktr);
    }
}

// ---------------------------------------------------------------------------
// K3: Apart[p][b][t][s] = sum_{k in chunk p} key[b,t,k]*ktr[b,s,k]
//     grid (6,32). NK=4. Single-pass fp16.
// ---------------------------------------------------------------------------
__global__ __launch_bounds__(256, 2) void k3_gemm_A()
{
    extern __shared__ __half dyn[];
    const int p = blockIdx.x;
    const int b = blockIdx.y;
    const int tid = threadIdx.x;
    const int warp = tid >> 5, lane = tid & 31;
    const int wm = warp >> 2, wn = warp & 3;

    unsigned sb = (unsigned)__cvta_generic_to_shared(dyn);

    const size_t base = (size_t)b * T_ * H_ + p * 128;
    const __half* Ah = &g_keyh[base];
    const __half* Bh = &g_ktrh[base];

    float acc[4][4][4];
#pragma unroll
    for (int i = 0; i < 4; i++)
#pragma unroll
        for (int j = 0; j < 4; j++)
#pragma unroll
            for (int r = 0; r < 4; r++) acc[i][j][r] = 0.f;

#define NK3 4
    {
        cpa_rm1(sb,                Ah, H_, tid);
        cpa_rm1(sb + RM_BUF_BYTES, Bh, H_, tid);
        CP_COMMIT();
    }
    for (int k = 0; k < NK3; k++) {
        CP_WAIT0();
        __syncthreads();
        if (k + 1 < NK3) {
            unsigned s1 = sb + (unsigned)(((k + 1) & 1) * RM_STAGE2_BYTES);
            cpa_rm1(s1,                Ah + (k + 1) * 32, H_, tid);
            cpa_rm1(s1 + RM_BUF_BYTES, Bh + (k + 1) * 32, H_, tid);
            CP_COMMIT();
        }
        unsigned s = sb + (unsigned)((k & 1) * RM_STAGE2_BYTES);
        mma_step_rm1(s, s + RM_BUF_BYTES, wm, wn, lane, acc);
    }
    epilogue(&g_Apart[(size_t)(p * B_ + b) * (T_ * T_)], T_, 1.f, wm, wn, lane, acc);
}

// ---------------------------------------------------------------------------
// K4: value-side scan, warp-autonomous 2-way split (proven core).
//     Writes vals f32 + vtr hi fp16.
// ---------------------------------------------------------------------------
#define K4_BLK 16

__global__ __launch_bounds__(512) void k4_scan_val(float* __restrict__ out)
{
    extern __shared__ float sm4[];
    float* A_s   = sm4;            // [t][s] 128*128
    float* vtr_s = sm4 + 16384;    // [s][lh] 128*256

    const int b    = blockIdx.x / 3;
    const int hb   = blockIdx.x % 3;
    const int tid  = threadIdx.x;
    const int warp = tid >> 5;
    const int lane = tid & 31;
    const int lr   = lane & 15;
    const int half = lane >> 4;
    const int lh   = warp * 16 + lr;
    const int h    = hb * 256 + lh;

    {
        const float* ap = &g_Apart[(size_t)b * (T_ * T_)];
        for (int e = tid * 4; e < T_ * T_; e += 512 * 4) {
            float4 s = *(const float4*)&ap[e];
#pragma unroll
            for (int p = 1; p < 6; p++) {
                float4 v = *(const float4*)&ap[(size_t)p * B_ * T_ * T_ + e];
                s.x += v.x; s.y += v.y; s.z += v.z; s.w += v.w;
            }
            *(float4*)&A_s[e] = s;
        }
    }
    __syncthreads();

    const float* ivp = &g_i[b * T_ * H2_ + H_ + h];
    const int gbase = (b * T_) * H_ + h;
    float* valso = &out[OUT_VALS_ + gbase];

    float vv = 0.f, vtr = 0.f;

    for (int t0 = 0; t0 < T_; t0 += K4_BLK) {
        float iv_blk[K4_BLK];
#pragma unroll
        for (int j = 0; j < K4_BLK; j++) iv_blk[j] = ivp[(t0 + j) * H2_];

        const int mid  = t0 >> 1;
        const int sbeg = half ? mid : 0;
        const int send = half ? t0  : mid;

        float acc[K4_BLK];
#pragma unroll
        for (int j = 0; j < K4_BLK; j++) acc[j] = 0.f;

        for (int s4 = sbeg; s4 < send; s4 += 4) {
            float v0 = vtr_s[(s4 + 0) * 256 + lh];
            float v1 = vtr_s[(s4 + 1) * 256 + lh];
            float v2 = vtr_s[(s4 + 2) * 256 + lh];
            float v3 = vtr_s[(s4 + 3) * 256 + lh];
#pragma unroll
            for (int j = 0; j < K4_BLK; j++) {
                float4 a = *(const float4*)&A_s[(t0 + j) * T_ + s4];
                acc[j] = fmaf(a.x, v0, acc[j]);
                acc[j] = fmaf(a.y, v1, acc[j]);
                acc[j] = fmaf(a.z, v2, acc[j]);
                acc[j] = fmaf(a.w, v3, acc[j]);
            }
        }
#pragma unroll
        for (int j = 0; j < K4_BLK; j++)
            acc[j] += __shfl_xor_sync(0xFFFFFFFFu, acc[j], 16);

        float vtr_blk[K4_BLK];
#pragma unroll
        for (int j = 0; j < K4_BLK; j++) {
            const int t = t0 + j;
            float a = acc[j];
            const float* Arow = &A_s[t * T_ + t0];
#pragma unroll
            for (int sj = 0; sj < j; sj++)
                a = fmaf(Arow[sj], vtr_blk[sj], a);
            float ikv = CIKV_ * a;

            vv = ALPHA_ * vv + OMA_ * (iv_blk[j] + ikv);
            float val = tanh_fast(vv);
            vtr = DTR_ * vtr + OMD_ * val;
            vtr_blk[j] = vtr;
            if (!half) {
                valso[t * H_] = val;
                vtr_s[t * 256 + lh] = vtr;
                g_vtrh[gbase + t * H_] = __float2half_rn(vtr);
            }
        }
        __syncwarp();
    }
}

// ---------------------------------------------------------------------------
// K5: mem[b][i][j] = eta * sum_s vtr[b,s,i]*ktr[b,s,j]
//     k-major fp16 single-pass, trans-ldmatrix. grid (6,6,32), NK=4.
// ---------------------------------------------------------------------------
__global__ __launch_bounds__(256, 2) void k5_gemm_mem(float* __restrict__ out)
{
    extern __shared__ __half dyn[];
    const int b  = blockIdx.z;
    const int i0 = blockIdx.y * 128;
    const int j0 = blockIdx.x * 128;
    const int tid = threadIdx.x;
    const int warp = tid >> 5, lane = tid & 31;
    const int wm = warp >> 2, wn = warp & 3;

    unsigned sb = (unsigned)__cvta_generic_to_shared(dyn);

    const size_t bb = (size_t)b * T_ * H_;
    const __half* Ah = &g_vtrh[bb + i0];
    const __half* Bh = &g_ktrh[bb + j0];

    float acc[4][4][4];
#pragma unroll
    for (int i = 0; i < 4; i++)
#pragma unroll
        for (int j = 0; j < 4; j++)
#pragma unroll
            for (int r = 0; r < 4; r++) acc[i][j][r] = 0.f;

#define NK5 4
    {
        cpa_km1(sb,                Ah, H_, tid);
        cpa_km1(sb + KM_BUF_BYTES, Bh, H_, tid);
        CP_COMMIT();
    }
    for (int k = 0; k < NK5; k++) {
        CP_WAIT0();
        __syncthreads();
        if (k + 1 < NK5) {
            unsigned s1 = sb + (unsigned)(((k + 1) & 1) * KM_STAGE2_BYTES);
            const size_t so = (size_t)(k + 1) * 32 * H_;
            cpa_km1(s1,                Ah + so, H_, tid);
            cpa_km1(s1 + KM_BUF_BYTES, Bh + so, H_, tid);
            CP_COMMIT();
        }
        unsigned s = sb + (unsigned)((k & 1) * KM_STAGE2_BYTES);
        mma_step_km1(s, s + KM_BUF_BYTES, wm, wn, lane, acc);
    }
    epilogue(&out[(size_t)b * (H_ * H_) + (size_t)i0 * H_ + j0], H_, ETA_,
             wm, wn, lane, acc);
}

// ---------------------------------------------------------------------------
extern "C" void kernel_launch(void* const* d_in, const int* in_sizes, int n_in,
                              void* d_out, int out_size)
{
    const float* x = (const float*)d_in[0];   // (32,128,256)
    const float* W = (const float*)d_in[1];   // (1536,256)
    float* out = (float*)d_out;               // mem | keys | vals

    const int smem_k1 = 2 * RM_STAGE3_BYTES;      // 61440
    const int smem_k3 = 2 * RM_STAGE2_BYTES;      // 40960
    const int smem_k5 = 2 * KM_STAGE2_BYTES;      // 34816
    const int smem_k4 = (16384 + 32768) * 4;      // 196608

    (void)cudaFuncSetAttribute(k1_gemm_in,
        cudaFuncAttributeMaxDynamicSharedMemorySize, smem_k1);
    (void)cudaFuncSetAttribute(k3_gemm_A,
        cudaFuncAttributeMaxDynamicSharedMemorySize, smem_k3);
    (void)cudaFuncSetAttribute(k5_gemm_mem,
        cudaFuncAttributeMaxDynamicSharedMemorySize, smem_k5);
    (void)cudaFuncSetAttribute(k4_scan_val,
        cudaFuncAttributeMaxDynamicSharedMemorySize, smem_k4);

    k0_convert<<<(XN_ + WN_ + 1023) / 1024, 256>>>(x, W);
    k1_gemm_in<<<dim3(12, 32), 256, smem_k1>>>();
    k2_scan_key<<<96, 256>>>(out);
    k3_gemm_A<<<dim3(6, 32), 256, smem_k3>>>();
    k4_scan_val<<<96, 512, smem_k4>>>(out);
    k5_gemm_mem<<<dim3(6, 6, 32), 256, smem_k5>>>(out);
}

// round 12
// speedup vs baseline: 1.4998x; 1.1239x over previous
#include <cuda_runtime.h>
#include <cuda_fp16.h>
#include <math.h>

// Problem constants
#define B_   32
#define T_   128
#define H_   768
#define IN_  256
#define H2_  1536

// exp(-1/20)
#define ALPHA_   0.951229424500714f
#define OMA_     0.048770575499286f
#define DTR_     0.951229424500714f
#define OMD_     0.048770575499286f
#define ETA_     0.1f
#define CIKV_    0.02f

// Output offsets (floats): mem | keys | vals
#define OUT_MEM_   0
#define OUT_KEYS_  18874368
#define OUT_VALS_  22020096

// Scratch (f32)
__device__ float g_i[B_ * T_ * H2_];
__device__ float g_Apart[6 * B_ * T_ * T_];

// fp16 operand arrays. x carries hi+lo (K1 2-pass); all others hi only.
__device__ __half g_xh[B_ * T_ * IN_],  g_xl[B_ * T_ * IN_];
__device__ __half g_Wh[H2_ * IN_];
__device__ __half g_keyh[B_ * T_ * H_];
__device__ __half g_ktrh[B_ * T_ * H_];
__device__ __half g_vtrh[B_ * T_ * H_];

__device__ __forceinline__ float tanh_fast(float x) {
    float y;
    asm("tanh.approx.f32 %0, %1;" : "=f"(y) : "f"(x));
    return y;
}
__device__ __forceinline__ void split_f16(float v, __half& hi, __half& lo) {
    hi = __float2half_rn(v);
    lo = __float2half_rn(v - __half2float(hi));
}

// ---------------------------------------------------------------------------
// mma.sync helpers (fp16, f32 accum)
// ---------------------------------------------------------------------------
__device__ __forceinline__ void ldsm_x4(unsigned addr, unsigned& r0, unsigned& r1,
                                        unsigned& r2, unsigned& r3) {
    asm volatile("ldmatrix.sync.aligned.m8n8.x4.shared.b16 {%0,%1,%2,%3}, [%4];"
                 : "=r"(r0), "=r"(r1), "=r"(r2), "=r"(r3) : "r"(addr));
}
__device__ __forceinline__ void ldsm_x4t(unsigned addr, unsigned& r0, unsigned& r1,
                                         unsigned& r2, unsigned& r3) {
    asm volatile("ldmatrix.sync.aligned.m8n8.x4.trans.shared.b16 {%0,%1,%2,%3}, [%4];"
                 : "=r"(r0), "=r"(r1), "=r"(r2), "=r"(r3) : "r"(addr));
}
__device__ __forceinline__ void mma16816(float* c, unsigned a0, unsigned a1,
                                         unsigned a2, unsigned a3,
                                         unsigned b0, unsigned b1) {
    asm volatile(
        "mma.sync.aligned.m16n8k16.row.col.f32.f16.f16.f32 "
        "{%0,%1,%2,%3}, {%4,%5,%6,%7}, {%8,%9}, {%0,%1,%2,%3};"
        : "+f"(c[0]), "+f"(c[1]), "+f"(c[2]), "+f"(c[3])
        : "r"(a0), "r"(a1), "r"(a2), "r"(a3), "r"(b0), "r"(b1));
}

// cp.async helpers
__device__ __forceinline__ void cp16(unsigned dst, const void* src) {
    asm volatile("cp.async.cg.shared.global [%0], [%1], 16;" :: "r"(dst), "l"(src));
}
#define CP_COMMIT() asm volatile("cp.async.commit_group;")
#define CP_WAIT0()  asm volatile("cp.async.wait_group 0;" ::: "memory")

#define SRM 40    // smem stride (halves) row-major tiles (128 rows x 32 k)
#define SKM 136   // smem stride (halves) k-major tiles (32 k x 128 m)
#define RM_BUF_HALVES (128 * SRM)            // 5120
#define RM_BUF_BYTES  (RM_BUF_HALVES * 2)    // 10240
#define RM_STAGE3_BYTES (3 * RM_BUF_BYTES)   // K1: Ah, Al, Bh
#define RM_STAGE2_BYTES (2 * RM_BUF_BYTES)   // K3: Ah, Bh
#define KM_BUF_HALVES (32 * SKM)             // 4352
#define KM_BUF_BYTES  (KM_BUF_HALVES * 2)    // 8704
#define KM_STAGE2_BYTES (2 * KM_BUF_BYTES)   // K5: Ah, Bh

// Copy one row-major 128x32 fp16 tile into smem via cp.async.
__device__ __forceinline__ void cpa_rm1(unsigned dst, const __half* src,
                                        int ld, int tid)
{
#pragma unroll
    for (int l = 0; l < 2; l++) {
        int c = tid + l * 256;
        int row = c >> 2;
        int q   = c & 3;
        cp16(dst + (unsigned)(row * SRM * 2 + q * 16),
             (const char*)src + (size_t)row * ld * 2 + q * 16);
    }
}
// Copy one k-major 32x128 fp16 tile into smem.
__device__ __forceinline__ void cpa_km1(unsigned dst, const __half* src,
                                        int ld, int tid)
{
#pragma unroll
    for (int l = 0; l < 2; l++) {
        int c = tid + l * 256;
        int row = c >> 4;
        int q   = c & 15;
        cp16(dst + (unsigned)(row * SKM * 2 + q * 16),
             (const char*)src + (size_t)row * ld * 2 + q * 16);
    }
}

// BK=32 compute step, row-major tiles, 2 A-passes (K1).
__device__ __forceinline__ void mma_step_rm2(
    unsigned bAh, unsigned bAl, unsigned bBh,
    int wm, int wn, int lane, float acc[4][4][4])
{
    const int lr = lane & 15;
    const int kh = (lane >> 4) * 8;
#pragma unroll
    for (int ks = 0; ks < 32; ks += 16) {
        unsigned ah[4][4], al[4][4], bh[4][2];
#pragma unroll
        for (int i = 0; i < 4; i++) {
            unsigned off = 2u * ((wm * 64 + i * 16 + lr) * SRM + ks + kh);
            ldsm_x4(bAh + off, ah[i][0], ah[i][1], ah[i][2], ah[i][3]);
            ldsm_x4(bAl + off, al[i][0], al[i][1], al[i][2], al[i][3]);
        }
#pragma unroll
        for (int p = 0; p < 2; p++) {
            unsigned off = 2u * ((wn * 32 + p * 16 + lr) * SRM + ks + kh);
            unsigned r0, r1, r2, r3;
            ldsm_x4(bBh + off, r0, r1, r2, r3);
            bh[p * 2 + 0][0] = r0; bh[p * 2 + 0][1] = r2;
            bh[p * 2 + 1][0] = r1; bh[p * 2 + 1][1] = r3;
        }
#pragma unroll
        for (int i = 0; i < 4; i++)
#pragma unroll
            for (int j = 0; j < 4; j++) {
                mma16816(acc[i][j], ah[i][0], ah[i][1], ah[i][2], ah[i][3],
                         bh[j][0], bh[j][1]);
                mma16816(acc[i][j], al[i][0], al[i][1], al[i][2], al[i][3],
                         bh[j][0], bh[j][1]);
            }
    }
}

// BK=32 compute step, row-major tiles, single pass (K3).
__device__ __forceinline__ void mma_step_rm1(
    unsigned bAh, unsigned bBh,
    int wm, int wn, int lane, float acc[4][4][4])
{
    const int lr = lane & 15;
    const int kh = (lane >> 4) * 8;
#pragma unroll
    for (int ks = 0; ks < 32; ks += 16) {
        unsigned ah[4][4], bh[4][2];
#pragma unroll
        for (int i = 0; i < 4; i++) {
            unsigned off = 2u * ((wm * 64 + i * 16 + lr) * SRM + ks + kh);
            ldsm_x4(bAh + off, ah[i][0], ah[i][1], ah[i][2], ah[i][3]);
        }
#pragma unroll
        for (int p = 0; p < 2; p++) {
            unsigned off = 2u * ((wn * 32 + p * 16 + lr) * SRM + ks + kh);
            unsigned r0, r1, r2, r3;
            ldsm_x4(bBh + off, r0, r1, r2, r3);
            bh[p * 2 + 0][0] = r0; bh[p * 2 + 0][1] = r2;
            bh[p * 2 + 1][0] = r1; bh[p * 2 + 1][1] = r3;
        }
#pragma unroll
        for (int i = 0; i < 4; i++)
#pragma unroll
            for (int j = 0; j < 4; j++)
                mma16816(acc[i][j], ah[i][0], ah[i][1], ah[i][2], ah[i][3],
                         bh[j][0], bh[j][1]);
    }
}

// BK=32 compute step, k-major tiles, single pass (K5).
__device__ __forceinline__ void mma_step_km1(
    unsigned bAh, unsigned bBh,
    int wm, int wn, int lane, float acc[4][4][4])
{
    const int krow = (lane & 7) + ((lane >> 4) << 3);
    const int mcol = ((lane >> 3) & 1) * 8;
#pragma unroll
    for (int ks = 0; ks < 32; ks += 16) {
        unsigned ah[4][4], bh[4][2];
#pragma unroll
        for (int i = 0; i < 4; i++) {
            unsigned off = 2u * ((ks + krow) * SKM + wm * 64 + i * 16 + mcol);
            ldsm_x4t(bAh + off, ah[i][0], ah[i][1], ah[i][2], ah[i][3]);
        }
#pragma unroll
        for (int p = 0; p < 2; p++) {
            unsigned off = 2u * ((ks + krow) * SKM + wn * 32 + p * 16 + mcol);
            unsigned r0, r1, r2, r3;
            ldsm_x4t(bBh + off, r0, r1, r2, r3);
            bh[p * 2 + 0][0] = r0; bh[p * 2 + 0][1] = r2;
            bh[p * 2 + 1][0] = r1; bh[p * 2 + 1][1] = r3;
        }
#pragma unroll
        for (int i = 0; i < 4; i++)
#pragma unroll
            for (int j = 0; j < 4; j++)
                mma16816(acc[i][j], ah[i][0], ah[i][1], ah[i][2], ah[i][3],
                         bh[j][0], bh[j][1]);
    }
}

// Epilogue: write 4x4 m16n8 tiles to gmem, scaled.
__device__ __forceinline__ void epilogue(float* dst, int ldc, float scale,
                                         int wm, int wn, int lane,
                                         float acc[4][4][4])
{
    const int r0 = lane >> 2;
    const int c0 = (lane & 3) * 2;
#pragma unroll
    for (int i = 0; i < 4; i++)
#pragma unroll
        for (int j = 0; j < 4; j++) {
            int row = wm * 64 + i * 16 + r0;
            int col = wn * 32 + j * 8 + c0;
            float2 v0 = make_float2(scale * acc[i][j][0], scale * acc[i][j][1]);
            float2 v1 = make_float2(scale * acc[i][j][2], scale * acc[i][j][3]);
            *(float2*)&dst[row * ldc + col] = v0;
            *(float2*)&dst[(row + 8) * ldc + col] = v1;
        }
}

// ---------------------------------------------------------------------------
// K0: pre-split x (hi+lo) and W (hi only) to fp16
// ---------------------------------------------------------------------------
#define XN_ (B_ * T_ * IN_)   // 1048576
#define WN_ (H2_ * IN_)       // 393216

__global__ __launch_bounds__(256) void k0_convert(
    const float* __restrict__ x, const float* __restrict__ W)
{
    int i4 = (blockIdx.x * 256 + threadIdx.x) * 4;
    if (i4 < XN_) {
        float4 v = *(const float4*)&x[i4];
        __half h0, l0, h1, l1, h2, l2, h3, l3;
        split_f16(v.x, h0, l0); split_f16(v.y, h1, l1);
        split_f16(v.z, h2, l2); split_f16(v.w, h3, l3);
        g_xh[i4 + 0] = h0; g_xh[i4 + 1] = h1; g_xh[i4 + 2] = h2; g_xh[i4 + 3] = h3;
        g_xl[i4 + 0] = l0; g_xl[i4 + 1] = l1; g_xl[i4 + 2] = l2; g_xl[i4 + 3] = l3;
    } else if (i4 < XN_ + WN_) {
        int off = i4 - XN_;
        float4 v = *(const float4*)&W[off];
        g_Wh[off + 0] = __float2half_rn(v.x);
        g_Wh[off + 1] = __float2half_rn(v.y);
        g_Wh[off + 2] = __float2half_rn(v.z);
        g_Wh[off + 3] = __float2half_rn(v.w);
    }
}

// ---------------------------------------------------------------------------
// K1: g_i[m][n] = sum_k x[m][k]*W[n][k]   M=4096 N=1536 K=256 (NK=8)
//     2-pass (x hi/lo), cp.async double-buffered. Dyn smem 61440B.
// ---------------------------------------------------------------------------
__global__ __launch_bounds__(256, 2) void k1_gemm_in()
{
    extern __shared__ __half dyn[];
    const int m0 = blockIdx.y * 128;
    const int n0 = blockIdx.x * 128;
    const int tid = threadIdx.x;
    const int warp = tid >> 5, lane = tid & 31;
    const int wm = warp >> 2, wn = warp & 3;

    unsigned sb = (unsigned)__cvta_generic_to_shared(dyn);

    float acc[4][4][4];
#pragma unroll
    for (int i = 0; i < 4; i++)
#pragma unroll
        for (int j = 0; j < 4; j++)
#pragma unroll
            for (int r = 0; r < 4; r++) acc[i][j][r] = 0.f;

    const __half* Ah = &g_xh[(size_t)m0 * IN_];
    const __half* Al = &g_xl[(size_t)m0 * IN_];
    const __half* Bh = &g_Wh[(size_t)n0 * IN_];

#define NK1 8
    {
        cpa_rm1(sb,                    Ah, IN_, tid);
        cpa_rm1(sb + RM_BUF_BYTES,     Al, IN_, tid);
        cpa_rm1(sb + 2 * RM_BUF_BYTES, Bh, IN_, tid);
        CP_COMMIT();
    }
    for (int k = 0; k < NK1; k++) {
        CP_WAIT0();
        __syncthreads();
        if (k + 1 < NK1) {
            unsigned s1 = sb + (unsigned)(((k + 1) & 1) * RM_STAGE3_BYTES);
            cpa_rm1(s1,                    Ah + (k + 1) * 32, IN_, tid);
            cpa_rm1(s1 + RM_BUF_BYTES,     Al + (k + 1) * 32, IN_, tid);
            cpa_rm1(s1 + 2 * RM_BUF_BYTES, Bh + (k + 1) * 32, IN_, tid);
            CP_COMMIT();
        }
        unsigned s = sb + (unsigned)((k & 1) * RM_STAGE3_BYTES);
        mma_step_rm2(s, s + RM_BUF_BYTES, s + 2 * RM_BUF_BYTES, wm, wn, lane, acc);
    }
    epilogue(&g_i[(size_t)m0 * H2_ + n0], H2_, 1.f, wm, wn, lane, acc);
}

// ---------------------------------------------------------------------------
// K2: key-side elementwise scan; writes keys f32, key hi, ktr hi (fp16)
// ---------------------------------------------------------------------------
__global__ __launch_bounds__(256) void k2_scan_key(float* __restrict__ out)
{
    const int b  = blockIdx.x / 3;
    const int h  = (blockIdx.x % 3) * 256 + threadIdx.x;

    const float* ik = &g_i[(b * T_) * H2_ + h];
    const int base = (b * T_) * H_ + h;
    float* keyso = &out[OUT_KEYS_ + base];

    float kv = 0.f, ktr = 0.f;
#pragma unroll 4
    for (int t = 0; t < T_; t++) {
        kv = ALPHA_ * kv + OMA_ * ik[t * H2_];
        float key = tanh_fast(kv);
        ktr = DTR_ * ktr + OMD_ * key;
        keyso[t * H_] = key;
        g_keyh[base + t * H_] = __float2half_rn(key);
        g_ktrh[base + t * H_] = __float2half_rn(ktr);
    }
}

// ---------------------------------------------------------------------------
// K3: Apart[p][b][t][s] = sum_{k in chunk p} key[b,t,k]*ktr[b,s,k]
//     grid (6,32). NK=4. Single-pass fp16.
// ---------------------------------------------------------------------------
__global__ __launch_bounds__(256, 2) void k3_gemm_A()
{
    extern __shared__ __half dyn[];
    const int p = blockIdx.x;
    const int b = blockIdx.y;
    const int tid = threadIdx.x;
    const int warp = tid >> 5, lane = tid & 31;
    const int wm = warp >> 2, wn = warp & 3;

    unsigned sb = (unsigned)__cvta_generic_to_shared(dyn);

    const size_t base = (size_t)b * T_ * H_ + p * 128;
    const __half* Ah = &g_keyh[base];
    const __half* Bh = &g_ktrh[base];

    float acc[4][4][4];
#pragma unroll
    for (int i = 0; i < 4; i++)
#pragma unroll
        for (int j = 0; j < 4; j++)
#pragma unroll
            for (int r = 0; r < 4; r++) acc[i][j][r] = 0.f;

#define NK3 4
    {
        cpa_rm1(sb,                Ah, H_, tid);
        cpa_rm1(sb + RM_BUF_BYTES, Bh, H_, tid);
        CP_COMMIT();
    }
    for (int k = 0; k < NK3; k++) {
        CP_WAIT0();
        __syncthreads();
        if (k + 1 < NK3) {
            unsigned s1 = sb + (unsigned)(((k + 1) & 1) * RM_STAGE2_BYTES);
            cpa_rm1(s1,                Ah + (k + 1) * 32, H_, tid);
            cpa_rm1(s1 + RM_BUF_BYTES, Bh + (k + 1) * 32, H_, tid);
            CP_COMMIT();
        }
        unsigned s = sb + (unsigned)((k & 1) * RM_STAGE2_BYTES);
        mma_step_rm1(s, s + RM_BUF_BYTES, wm, wn, lane, acc);
    }
    epilogue(&g_Apart[(size_t)(p * B_ + b) * (T_ * T_)], T_, 1.f, wm, wn, lane, acc);
}

// ---------------------------------------------------------------------------
// K4: value-side scan with TENSOR-CORE cross phase.
//     grid 96 (b x 3 h-blocks of 256), 256 threads = 8 warps.
//     Per t-block of 16:
//       cross: D[16t x 256h] = A[16 x t0] @ vtr[t0 x 256] via mma.m16n8k16
//              (A fp16 smem row-major, proven no-trans ldmatrix A pattern;
//               vtr fp16 smem [s][h], proven trans-ldmatrix B pattern)
//       stage D through smem; intra: thread-owns-h serial triangle + tanh.
//     Strides 136/264/260 halves|floats: row-step mod 128B = 16 -> conflict-free.
//     Dyn smem: A 34816 + vtr 67584 + p 16640 = 119040 B.
// ---------------------------------------------------------------------------
#define SA4 136   // A_s16 stride (halves)
#define SV4 264   // vtr16 stride (halves)
#define SP4 260   // p_s stride (floats)
#define K4_SMEM (128 * SA4 * 2 + 128 * SV4 * 2 + 16 * SP4 * 4)

__global__ __launch_bounds__(256) void k4_scan_val(float* __restrict__ out)
{
    extern __shared__ char sm4raw[];
    __half* A_s16 = (__half*)sm4raw;                              // [128][SA4]
    __half* vtr16 = (__half*)(sm4raw + 128 * SA4 * 2);            // [128][SV4]
    float*  p_s   = (float*)(sm4raw + 128 * SA4 * 2 + 128 * SV4 * 2); // [16][SP4]

    const int b    = blockIdx.x / 3;
    const int hb   = blockIdx.x % 3;
    const int tid  = threadIdx.x;
    const int warp = tid >> 5;
    const int lane = tid & 31;
    const int h    = hb * 256 + tid;

    // A-sum: 6 K-split partials -> fp16 A_s16 (padded rows)
    {
        const float* ap = &g_Apart[(size_t)b * (T_ * T_)];
        for (int e = tid * 4; e < T_ * T_; e += 256 * 4) {
            float4 s = *(const float4*)&ap[e];
#pragma unroll
            for (int p = 1; p < 6; p++) {
                float4 v = *(const float4*)&ap[(size_t)p * B_ * T_ * T_ + e];
                s.x += v.x; s.y += v.y; s.z += v.z; s.w += v.w;
            }
            int t = e >> 7, sc = e & 127;
            __half* d = &A_s16[t * SA4 + sc];
            d[0] = __float2half_rn(s.x);
            d[1] = __float2half_rn(s.y);
            d[2] = __float2half_rn(s.z);
            d[3] = __float2half_rn(s.w);
        }
    }
    __syncthreads();

    const float* ivp = &g_i[b * T_ * H2_ + H_ + h];
    const int gbase = (b * T_) * H_ + h;
    float* valso = &out[OUT_VALS_ + gbase];

    unsigned aA = (unsigned)__cvta_generic_to_shared(A_s16);
    unsigned aV = (unsigned)__cvta_generic_to_shared(vtr16);

    // fragment index helpers (proven patterns)
    const int lr   = lane & 15;                      // A: row within m16
    const int kh   = (lane >> 4) * 8;                // A: k-half
    const int krow = (lane & 7) + ((lane >> 4) << 3);// B: k row
    const int mcol = ((lane >> 3) & 1) * 8;          // B: n col within 16
    const int r0w  = lane >> 2;                      // D: row
    const int c0w  = (lane & 3) * 2;                 // D: col pair

    float vv = 0.f, vtr = 0.f;

    for (int t0 = 0; t0 < T_; t0 += 16) {
        float iv_blk[16];
#pragma unroll
        for (int j = 0; j < 16; j++) iv_blk[j] = ivp[(t0 + j) * H2_];

        // ---- cross phase: mma over s in [0, t0) ----
        if (t0 > 0) {
            float c[4][4];
#pragma unroll
            for (int j = 0; j < 4; j++)
#pragma unroll
                for (int r = 0; r < 4; r++) c[j][r] = 0.f;

            for (int ks = 0; ks < t0; ks += 16) {
                unsigned af0, af1, af2, af3;
                ldsm_x4(aA + 2u * ((t0 + lr) * SA4 + ks + kh), af0, af1, af2, af3);
                unsigned bf[4][2];
#pragma unroll
                for (int p = 0; p < 2; p++) {
                    unsigned r0, r1, r2, r3;
                    ldsm_x4t(aV + 2u * ((ks + krow) * SV4 + warp * 32 + p * 16 + mcol),
                             r0, r1, r2, r3);
                    bf[p * 2 + 0][0] = r0; bf[p * 2 + 0][1] = r2;
                    bf[p * 2 + 1][0] = r1; bf[p * 2 + 1][1] = r3;
                }
#pragma unroll
                for (int j = 0; j < 4; j++)
                    mma16816(c[j], af0, af1, af2, af3, bf[j][0], bf[j][1]);
            }
            // stage D tile into p_s
#pragma unroll
            for (int j = 0; j < 4; j++) {
                int col = warp * 32 + j * 8 + c0w;
                p_s[r0w * SP4 + col]           = c[j][0];
                p_s[r0w * SP4 + col + 1]       = c[j][1];
                p_s[(r0w + 8) * SP4 + col]     = c[j][2];
                p_s[(r0w + 8) * SP4 + col + 1] = c[j][3];
            }
        }
        __syncthreads();

        // ---- intra phase: thread owns h = tid ----
        float vtr_blk[16];
#pragma unroll
        for (int j = 0; j < 16; j++) {
            const int t = t0 + j;
            float a = (t0 > 0) ? p_s[j * SP4 + tid] : 0.f;
#pragma unroll
            for (int sj = 0; sj < j; sj++)
                a = fmaf(__half2float(A_s16[t * SA4 + t0 + sj]), vtr_blk[sj], a);
            float ikv = CIKV_ * a;

            vv = ALPHA_ * vv + OMA_ * (iv_blk[j] + ikv);
            float val = tanh_fast(vv);
            vtr = DTR_ * vtr + OMD_ * val;
            vtr_blk[j] = vtr;

            valso[t * H_] = val;
            __half v16 = __float2half_rn(vtr);
            vtr16[t * SV4 + tid] = v16;
            g_vtrh[gbase + t * H_] = v16;
        }
        __syncthreads();
    }
}

// ---------------------------------------------------------------------------
// K5: mem[b][i][j] = eta * sum_s vtr[b,s,i]*ktr[b,s,j]
//     k-major fp16 single-pass, trans-ldmatrix. grid (6,6,32), NK=4.
// ---------------------------------------------------------------------------
__global__ __launch_bounds__(256, 2) void k5_gemm_mem(float* __restrict__ out)
{
    extern __shared__ __half dyn[];
    const int b  = blockIdx.z;
    const int i0 = blockIdx.y * 128;
    const int j0 = blockIdx.x * 128;
    const int tid = threadIdx.x;
    const int warp = tid >> 5, lane = tid & 31;
    const int wm = warp >> 2, wn = warp & 3;

    unsigned sb = (unsigned)__cvta_generic_to_shared(dyn);

    const size_t bb = (size_t)b * T_ * H_;
    const __half* Ah = &g_vtrh[bb + i0];
    const __half* Bh = &g_ktrh[bb + j0];

    float acc[4][4][4];
#pragma unroll
    for (int i = 0; i < 4; i++)
#pragma unroll
        for (int j = 0; j < 4; j++)
#pragma unroll
            for (int r = 0; r < 4; r++) acc[i][j][r] = 0.f;

#define NK5 4
    {
        cpa_km1(sb,                Ah, H_, tid);
        cpa_km1(sb + KM_BUF_BYTES, Bh, H_, tid);
        CP_COMMIT();
    }
    for (int k = 0; k < NK5; k++) {
        CP_WAIT0();
        __syncthreads();
        if (k + 1 < NK5) {
            unsigned s1 = sb + (unsigned)(((k + 1) & 1) * KM_STAGE2_BYTES);
            const size_t so = (size_t)(k + 1) * 32 * H_;
            cpa_km1(s1,                Ah + so, H_, tid);
            cpa_km1(s1 + KM_BUF_BYTES, Bh + so, H_, tid);
            CP_COMMIT();
        }
        unsigned s = sb + (unsigned)((k & 1) * KM_STAGE2_BYTES);
        mma_step_km1(s, s + KM_BUF_BYTES, wm, wn, lane, acc);
    }
    epilogue(&out[(size_t)b * (H_ * H_) + (size_t)i0 * H_ + j0], H_, ETA_,
             wm, wn, lane, acc);
}

// ---------------------------------------------------------------------------
extern "C" void kernel_launch(void* const* d_in, const int* in_sizes, int n_in,
                              void* d_out, int out_size)
{
    const float* x = (const float*)d_in[0];   // (32,128,256)
    const float* W = (const float*)d_in[1];   // (1536,256)
    float* out = (float*)d_out;               // mem | keys | vals

    const int smem_k1 = 2 * RM_STAGE3_BYTES;      // 61440
    const int smem_k3 = 2 * RM_STAGE2_BYTES;      // 40960
    const int smem_k5 = 2 * KM_STAGE2_BYTES;      // 34816

    (void)cudaFuncSetAttribute(k1_gemm_in,
        cudaFuncAttributeMaxDynamicSharedMemorySize, smem_k1);
    (void)cudaFuncSetAttribute(k3_gemm_A,
        cudaFuncAttributeMaxDynamicSharedMemorySize, smem_k3);
    (void)cudaFuncSetAttribute(k5_gemm_mem,
        cudaFuncAttributeMaxDynamicSharedMemorySize, smem_k5);
    (void)cudaFuncSetAttribute(k4_scan_val,
        cudaFuncAttributeMaxDynamicSharedMemorySize, K4_SMEM);

    k0_convert<<<(XN_ + WN_ + 1023) / 1024, 256>>>(x, W);
    k1_gemm_in<<<dim3(12, 32), 256, smem_k1>>>();
    k2_scan_key<<<96, 256>>>(out);
    k3_gemm_A<<<dim3(6, 32), 256, smem_k3>>>();
    k4_scan_val<<<96, 256, K4_SMEM>>>(out);
    k5_gemm_mem<<<dim3(6, 6, 32), 256, smem_k5>>>(out);
}

// round 13
// speedup vs baseline: 1.6496x; 1.0999x over previous
#include <cuda_runtime.h>
#include <cuda_fp16.h>
#include <math.h>

// Problem constants
#define B_   32
#define T_   128
#define H_   768
#define IN_  256
#define H2_  1536

// exp(-1/20)
#define ALPHA_   0.951229424500714f
#define OMA_     0.048770575499286f
#define DTR_     0.951229424500714f
#define OMD_     0.048770575499286f
#define ETA_     0.1f
#define CIKV_    0.02f

// Output offsets (floats): mem | keys | vals
#define OUT_MEM_   0
#define OUT_KEYS_  18874368
#define OUT_VALS_  22020096

// Scratch (f32)
__device__ float g_i[B_ * T_ * H2_];
__device__ float g_Apart[6 * B_ * T_ * T_];

// fp16 operand arrays (all single-rounded)
__device__ __half g_xh[B_ * T_ * IN_];
__device__ __half g_Wh[H2_ * IN_];
__device__ __half g_keyh[B_ * T_ * H_];
__device__ __half g_ktrh[B_ * T_ * H_];
__device__ __half g_vtrh[B_ * T_ * H_];

__device__ __forceinline__ float tanh_fast(float x) {
    float y;
    asm("tanh.approx.f32 %0, %1;" : "=f"(y) : "f"(x));
    return y;
}

// ---------------------------------------------------------------------------
// mma.sync helpers (fp16, f32 accum)
// ---------------------------------------------------------------------------
__device__ __forceinline__ void ldsm_x4(unsigned addr, unsigned& r0, unsigned& r1,
                                        unsigned& r2, unsigned& r3) {
    asm volatile("ldmatrix.sync.aligned.m8n8.x4.shared.b16 {%0,%1,%2,%3}, [%4];"
                 : "=r"(r0), "=r"(r1), "=r"(r2), "=r"(r3) : "r"(addr));
}
__device__ __forceinline__ void ldsm_x4t(unsigned addr, unsigned& r0, unsigned& r1,
                                         unsigned& r2, unsigned& r3) {
    asm volatile("ldmatrix.sync.aligned.m8n8.x4.trans.shared.b16 {%0,%1,%2,%3}, [%4];"
                 : "=r"(r0), "=r"(r1), "=r"(r2), "=r"(r3) : "r"(addr));
}
__device__ __forceinline__ void mma16816(float* c, unsigned a0, unsigned a1,
                                         unsigned a2, unsigned a3,
                                         unsigned b0, unsigned b1) {
    asm volatile(
        "mma.sync.aligned.m16n8k16.row.col.f32.f16.f16.f32 "
        "{%0,%1,%2,%3}, {%4,%5,%6,%7}, {%8,%9}, {%0,%1,%2,%3};"
        : "+f"(c[0]), "+f"(c[1]), "+f"(c[2]), "+f"(c[3])
        : "r"(a0), "r"(a1), "r"(a2), "r"(a3), "r"(b0), "r"(b1));
}

// cp.async helpers
__device__ __forceinline__ void cp16(unsigned dst, const void* src) {
    asm volatile("cp.async.cg.shared.global [%0], [%1], 16;" :: "r"(dst), "l"(src));
}
#define CP_COMMIT() asm volatile("cp.async.commit_group;")
#define CP_WAIT0()  asm volatile("cp.async.wait_group 0;" ::: "memory")

#define SRM 40    // smem stride (halves) row-major tiles (128 rows x 32 k)
#define SKM 136   // smem stride (halves) k-major tiles (32 k x 128 m)
#define RM_BUF_HALVES (128 * SRM)            // 5120
#define RM_BUF_BYTES  (RM_BUF_HALVES * 2)    // 10240
#define RM_STAGE2_BYTES (2 * RM_BUF_BYTES)   // K1/K3: Ah, Bh
#define KM_BUF_HALVES (32 * SKM)             // 4352
#define KM_BUF_BYTES  (KM_BUF_HALVES * 2)    // 8704
#define KM_STAGE2_BYTES (2 * KM_BUF_BYTES)   // K5: Ah, Bh

// Copy one row-major 128x32 fp16 tile into smem via cp.async.
__device__ __forceinline__ void cpa_rm1(unsigned dst, const __half* src,
                                        int ld, int tid)
{
#pragma unroll
    for (int l = 0; l < 2; l++) {
        int c = tid + l * 256;
        int row = c >> 2;
        int q   = c & 3;
        cp16(dst + (unsigned)(row * SRM * 2 + q * 16),
             (const char*)src + (size_t)row * ld * 2 + q * 16);
    }
}
// Copy one k-major 32x128 fp16 tile into smem.
__device__ __forceinline__ void cpa_km1(unsigned dst, const __half* src,
                                        int ld, int tid)
{
#pragma unroll
    for (int l = 0; l < 2; l++) {
        int c = tid + l * 256;
        int row = c >> 4;
        int q   = c & 15;
        cp16(dst + (unsigned)(row * SKM * 2 + q * 16),
             (const char*)src + (size_t)row * ld * 2 + q * 16);
    }
}

// BK=32 compute step, row-major tiles, single pass (K1/K3).
__device__ __forceinline__ void mma_step_rm1(
    unsigned bAh, unsigned bBh,
    int wm, int wn, int lane, float acc[4][4][4])
{
    const int lr = lane & 15;
    const int kh = (lane >> 4) * 8;
#pragma unroll
    for (int ks = 0; ks < 32; ks += 16) {
        unsigned ah[4][4], bh[4][2];
#pragma unroll
        for (int i = 0; i < 4; i++) {
            unsigned off = 2u * ((wm * 64 + i * 16 + lr) * SRM + ks + kh);
            ldsm_x4(bAh + off, ah[i][0], ah[i][1], ah[i][2], ah[i][3]);
        }
#pragma unroll
        for (int p = 0; p < 2; p++) {
            unsigned off = 2u * ((wn * 32 + p * 16 + lr) * SRM + ks + kh);
            unsigned r0, r1, r2, r3;
            ldsm_x4(bBh + off, r0, r1, r2, r3);
            bh[p * 2 + 0][0] = r0; bh[p * 2 + 0][1] = r2;
            bh[p * 2 + 1][0] = r1; bh[p * 2 + 1][1] = r3;
        }
#pragma unroll
        for (int i = 0; i < 4; i++)
#pragma unroll
            for (int j = 0; j < 4; j++)
                mma16816(acc[i][j], ah[i][0], ah[i][1], ah[i][2], ah[i][3],
                         bh[j][0], bh[j][1]);
    }
}

// BK=32 compute step, k-major tiles, single pass (K5).
__device__ __forceinline__ void mma_step_km1(
    unsigned bAh, unsigned bBh,
    int wm, int wn, int lane, float acc[4][4][4])
{
    const int krow = (lane & 7) + ((lane >> 4) << 3);
    const int mcol = ((lane >> 3) & 1) * 8;
#pragma unroll
    for (int ks = 0; ks < 32; ks += 16) {
        unsigned ah[4][4], bh[4][2];
#pragma unroll
        for (int i = 0; i < 4; i++) {
            unsigned off = 2u * ((ks + krow) * SKM + wm * 64 + i * 16 + mcol);
            ldsm_x4t(bAh + off, ah[i][0], ah[i][1], ah[i][2], ah[i][3]);
        }
#pragma unroll
        for (int p = 0; p < 2; p++) {
            unsigned off = 2u * ((ks + krow) * SKM + wn * 32 + p * 16 + mcol);
            unsigned r0, r1, r2, r3;
            ldsm_x4t(bBh + off, r0, r1, r2, r3);
            bh[p * 2 + 0][0] = r0; bh[p * 2 + 0][1] = r2;
            bh[p * 2 + 1][0] = r1; bh[p * 2 + 1][1] = r3;
        }
#pragma unroll
        for (int i = 0; i < 4; i++)
#pragma unroll
            for (int j = 0; j < 4; j++)
                mma16816(acc[i][j], ah[i][0], ah[i][1], ah[i][2], ah[i][3],
                         bh[j][0], bh[j][1]);
    }
}

// Epilogue: write 4x4 m16n8 tiles to gmem, scaled.
__device__ __forceinline__ void epilogue(float* dst, int ldc, float scale,
                                         int wm, int wn, int lane,
                                         float acc[4][4][4])
{
    const int r0 = lane >> 2;
    const int c0 = (lane & 3) * 2;
#pragma unroll
    for (int i = 0; i < 4; i++)
#pragma unroll
        for (int j = 0; j < 4; j++) {
            int row = wm * 64 + i * 16 + r0;
            int col = wn * 32 + j * 8 + c0;
            float2 v0 = make_float2(scale * acc[i][j][0], scale * acc[i][j][1]);
            float2 v1 = make_float2(scale * acc[i][j][2], scale * acc[i][j][3]);
            *(float2*)&dst[row * ldc + col] = v0;
            *(float2*)&dst[(row + 8) * ldc + col] = v1;
        }
}

// ---------------------------------------------------------------------------
// K0: round x and W to fp16 (single rounding each)
// ---------------------------------------------------------------------------
#define XN_ (B_ * T_ * IN_)   // 1048576
#define WN_ (H2_ * IN_)       // 393216

__global__ __launch_bounds__(256) void k0_convert(
    const float* __restrict__ x, const float* __restrict__ W)
{
    int i4 = (blockIdx.x * 256 + threadIdx.x) * 4;
    if (i4 < XN_) {
        float4 v = *(const float4*)&x[i4];
        g_xh[i4 + 0] = __float2half_rn(v.x);
        g_xh[i4 + 1] = __float2half_rn(v.y);
        g_xh[i4 + 2] = __float2half_rn(v.z);
        g_xh[i4 + 3] = __float2half_rn(v.w);
    } else if (i4 < XN_ + WN_) {
        int off = i4 - XN_;
        float4 v = *(const float4*)&W[off];
        g_Wh[off + 0] = __float2half_rn(v.x);
        g_Wh[off + 1] = __float2half_rn(v.y);
        g_Wh[off + 2] = __float2half_rn(v.z);
        g_Wh[off + 3] = __float2half_rn(v.w);
    }
}

// ---------------------------------------------------------------------------
// K1: g_i[m][n] = sum_k x[m][k]*W[n][k]   M=4096 N=1536 K=256 (NK=8)
//     single-pass fp16, cp.async double-buffered. Dyn smem 40960B.
// ---------------------------------------------------------------------------
__global__ __launch_bounds__(256, 2) void k1_gemm_in()
{
    extern __shared__ __half dyn[];
    const int m0 = blockIdx.y * 128;
    const int n0 = blockIdx.x * 128;
    const int tid = threadIdx.x;
    const int warp = tid >> 5, lane = tid & 31;
    const int wm = warp >> 2, wn = warp & 3;

    unsigned sb = (unsigned)__cvta_generic_to_shared(dyn);

    float acc[4][4][4];
#pragma unroll
    for (int i = 0; i < 4; i++)
#pragma unroll
        for (int j = 0; j < 4; j++)
#pragma unroll
            for (int r = 0; r < 4; r++) acc[i][j][r] = 0.f;

    const __half* Ah = &g_xh[(size_t)m0 * IN_];
    const __half* Bh = &g_Wh[(size_t)n0 * IN_];

#define NK1 8
    {
        cpa_rm1(sb,                Ah, IN_, tid);
        cpa_rm1(sb + RM_BUF_BYTES, Bh, IN_, tid);
        CP_COMMIT();
    }
    for (int k = 0; k < NK1; k++) {
        CP_WAIT0();
        __syncthreads();
        if (k + 1 < NK1) {
            unsigned s1 = sb + (unsigned)(((k + 1) & 1) * RM_STAGE2_BYTES);
            cpa_rm1(s1,                Ah + (k + 1) * 32, IN_, tid);
            cpa_rm1(s1 + RM_BUF_BYTES, Bh + (k + 1) * 32, IN_, tid);
            CP_COMMIT();
        }
        unsigned s = sb + (unsigned)((k & 1) * RM_STAGE2_BYTES);
        mma_step_rm1(s, s + RM_BUF_BYTES, wm, wn, lane, acc);
    }
    epilogue(&g_i[(size_t)m0 * H2_ + n0], H2_, 1.f, wm, wn, lane, acc);
}

// ---------------------------------------------------------------------------
// K2: key-side elementwise scan; writes keys f32, key hi, ktr hi (fp16)
// ---------------------------------------------------------------------------
__global__ __launch_bounds__(256) void k2_scan_key(float* __restrict__ out)
{
    const int b  = blockIdx.x / 3;
    const int h  = (blockIdx.x % 3) * 256 + threadIdx.x;

    const float* ik = &g_i[(b * T_) * H2_ + h];
    const int base = (b * T_) * H_ + h;
    float* keyso = &out[OUT_KEYS_ + base];

    float kv = 0.f, ktr = 0.f;
#pragma unroll 4
    for (int t = 0; t < T_; t++) {
        kv = ALPHA_ * kv + OMA_ * ik[t * H2_];
        float key = tanh_fast(kv);
        ktr = DTR_ * ktr + OMD_ * key;
        keyso[t * H_] = key;
        g_keyh[base + t * H_] = __float2half_rn(key);
        g_ktrh[base + t * H_] = __float2half_rn(ktr);
    }
}

// ---------------------------------------------------------------------------
// K3: Apart[p][b][t][s] = sum_{k in chunk p} key[b,t,k]*ktr[b,s,k]
//     grid (6,32). NK=4. Single-pass fp16.
// ---------------------------------------------------------------------------
__global__ __launch_bounds__(256, 2) void k3_gemm_A()
{
    extern __shared__ __half dyn[];
    const int p = blockIdx.x;
    const int b = blockIdx.y;
    const int tid = threadIdx.x;
    const int warp = tid >> 5, lane = tid & 31;
    const int wm = warp >> 2, wn = warp & 3;

    unsigned sb = (unsigned)__cvta_generic_to_shared(dyn);

    const size_t base = (size_t)b * T_ * H_ + p * 128;
    const __half* Ah = &g_keyh[base];
    const __half* Bh = &g_ktrh[base];

    float acc[4][4][4];
#pragma unroll
    for (int i = 0; i < 4; i++)
#pragma unroll
        for (int j = 0; j < 4; j++)
#pragma unroll
            for (int r = 0; r < 4; r++) acc[i][j][r] = 0.f;

#define NK3 4
    {
        cpa_rm1(sb,                Ah, H_, tid);
        cpa_rm1(sb + RM_BUF_BYTES, Bh, H_, tid);
        CP_COMMIT();
    }
    for (int k = 0; k < NK3; k++) {
        CP_WAIT0();
        __syncthreads();
        if (k + 1 < NK3) {
            unsigned s1 = sb + (unsigned)(((k + 1) & 1) * RM_STAGE2_BYTES);
            cpa_rm1(s1,                Ah + (k + 1) * 32, H_, tid);
            cpa_rm1(s1 + RM_BUF_BYTES, Bh + (k + 1) * 32, H_, tid);
            CP_COMMIT();
        }
        unsigned s = sb + (unsigned)((k & 1) * RM_STAGE2_BYTES);
        mma_step_rm1(s, s + RM_BUF_BYTES, wm, wn, lane, acc);
    }
    epilogue(&g_Apart[(size_t)(p * B_ + b) * (T_ * T_)], T_, 1.f, wm, wn, lane, acc);
}

// ---------------------------------------------------------------------------
// K4: value-side scan with tensor-core cross phase (proven R11 core).
// ---------------------------------------------------------------------------
#define SA4 136   // A_s16 stride (halves)
#define SV4 264   // vtr16 stride (halves)
#define SP4 260   // p_s stride (floats)
#define K4_SMEM (128 * SA4 * 2 + 128 * SV4 * 2 + 16 * SP4 * 4)

__global__ __launch_bounds__(256) void k4_scan_val(float* __restrict__ out)
{
    extern __shared__ char sm4raw[];
    __half* A_s16 = (__half*)sm4raw;                              // [128][SA4]
    __half* vtr16 = (__half*)(sm4raw + 128 * SA4 * 2);            // [128][SV4]
    float*  p_s   = (float*)(sm4raw + 128 * SA4 * 2 + 128 * SV4 * 2); // [16][SP4]

    const int b    = blockIdx.x / 3;
    const int hb   = blockIdx.x % 3;
    const int tid  = threadIdx.x;
    const int warp = tid >> 5;
    const int lane = tid & 31;
    const int h    = hb * 256 + tid;

    // A-sum: 6 K-split partials -> fp16 A_s16 (padded rows)
    {
        const float* ap = &g_Apart[(size_t)b * (T_ * T_)];
        for (int e = tid * 4; e < T_ * T_; e += 256 * 4) {
            float4 s = *(const float4*)&ap[e];
#pragma unroll
            for (int p = 1; p < 6; p++) {
                float4 v = *(const float4*)&ap[(size_t)p * B_ * T_ * T_ + e];
                s.x += v.x; s.y += v.y; s.z += v.z; s.w += v.w;
            }
            int t = e >> 7, sc = e & 127;
            __half* d = &A_s16[t * SA4 + sc];
            d[0] = __float2half_rn(s.x);
            d[1] = __float2half_rn(s.y);
            d[2] = __float2half_rn(s.z);
            d[3] = __float2half_rn(s.w);
        }
    }
    __syncthreads();

    const float* ivp = &g_i[b * T_ * H2_ + H_ + h];
    const int gbase = (b * T_) * H_ + h;
    float* valso = &out[OUT_VALS_ + gbase];

    unsigned aA = (unsigned)__cvta_generic_to_shared(A_s16);
    unsigned aV = (unsigned)__cvta_generic_to_shared(vtr16);

    const int lr   = lane & 15;
    const int kh   = (lane >> 4) * 8;
    const int krow = (lane & 7) + ((lane >> 4) << 3);
    const int mcol = ((lane >> 3) & 1) * 8;
    const int r0w  = lane >> 2;
    const int c0w  = (lane & 3) * 2;

    float vv = 0.f, vtr = 0.f;

    for (int t0 = 0; t0 < T_; t0 += 16) {
        float iv_blk[16];
#pragma unroll
        for (int j = 0; j < 16; j++) iv_blk[j] = ivp[(t0 + j) * H2_];

        // ---- cross phase: mma over s in [0, t0) ----
        if (t0 > 0) {
            float c[4][4];
#pragma unroll
            for (int j = 0; j < 4; j++)
#pragma unroll
                for (int r = 0; r < 4; r++) c[j][r] = 0.f;

            for (int ks = 0; ks < t0; ks += 16) {
                unsigned af0, af1, af2, af3;
                ldsm_x4(aA + 2u * ((t0 + lr) * SA4 + ks + kh), af0, af1, af2, af3);
                unsigned bf[4][2];
#pragma unroll
                for (int p = 0; p < 2; p++) {
                    unsigned r0, r1, r2, r3;
                    ldsm_x4t(aV + 2u * ((ks + krow) * SV4 + warp * 32 + p * 16 + mcol),
                             r0, r1, r2, r3);
                    bf[p * 2 + 0][0] = r0; bf[p * 2 + 0][1] = r2;
                    bf[p * 2 + 1][0] = r1; bf[p * 2 + 1][1] = r3;
                }
#pragma unroll
                for (int j = 0; j < 4; j++)
                    mma16816(c[j], af0, af1, af2, af3, bf[j][0], bf[j][1]);
            }
#pragma unroll
            for (int j = 0; j < 4; j++) {
                int col = warp * 32 + j * 8 + c0w;
                p_s[r0w * SP4 + col]           = c[j][0];
                p_s[r0w * SP4 + col + 1]       = c[j][1];
                p_s[(r0w + 8) * SP4 + col]     = c[j][2];
                p_s[(r0w + 8) * SP4 + col + 1] = c[j][3];
            }
        }
        __syncthreads();

        // ---- intra phase: thread owns h = tid ----
        float vtr_blk[16];
#pragma unroll
        for (int j = 0; j < 16; j++) {
            const int t = t0 + j;
            float a = (t0 > 0) ? p_s[j * SP4 + tid] : 0.f;
#pragma unroll
            for (int sj = 0; sj < j; sj++)
                a = fmaf(__half2float(A_s16[t * SA4 + t0 + sj]), vtr_blk[sj], a);
            float ikv = CIKV_ * a;

            vv = ALPHA_ * vv + OMA_ * (iv_blk[j] + ikv);
            float val = tanh_fast(vv);
            vtr = DTR_ * vtr + OMD_ * val;
            vtr_blk[j] = vtr;

            valso[t * H_] = val;
            __half v16 = __float2half_rn(vtr);
            vtr16[t * SV4 + tid] = v16;
            g_vtrh[gbase + t * H_] = v16;
        }
        __syncthreads();
    }
}

// ---------------------------------------------------------------------------
// K5: mem[b][i][j] = eta * sum_s vtr[b,s,i]*ktr[b,s,j]
//     k-major fp16 single-pass, trans-ldmatrix. grid (6,6,32), NK=4.
// ---------------------------------------------------------------------------
__global__ __launch_bounds__(256, 2) void k5_gemm_mem(float* __restrict__ out)
{
    extern __shared__ __half dyn[];
    const int b  = blockIdx.z;
    const int i0 = blockIdx.y * 128;
    const int j0 = blockIdx.x * 128;
    const int tid = threadIdx.x;
    const int warp = tid >> 5, lane = tid & 31;
    const int wm = warp >> 2, wn = warp & 3;

    unsigned sb = (unsigned)__cvta_generic_to_shared(dyn);

    const size_t bb = (size_t)b * T_ * H_;
    const __half* Ah = &g_vtrh[bb + i0];
    const __half* Bh = &g_ktrh[bb + j0];

    float acc[4][4][4];
#pragma unroll
    for (int i = 0; i < 4; i++)
#pragma unroll
        for (int j = 0; j < 4; j++)
#pragma unroll
            for (int r = 0; r < 4; r++) acc[i][j][r] = 0.f;

#define NK5 4
    {
        cpa_km1(sb,                Ah, H_, tid);
        cpa_km1(sb + KM_BUF_BYTES, Bh, H_, tid);
        CP_COMMIT();
    }
    for (int k = 0; k < NK5; k++) {
        CP_WAIT0();
        __syncthreads();
        if (k + 1 < NK5) {
            unsigned s1 = sb + (unsigned)(((k + 1) & 1) * KM_STAGE2_BYTES);
            const size_t so = (size_t)(k + 1) * 32 * H_;
            cpa_km1(s1,                Ah + so, H_, tid);
            cpa_km1(s1 + KM_BUF_BYTES, Bh + so, H_, tid);
            CP_COMMIT();
        }
        unsigned s = sb + (unsigned)((k & 1) * KM_STAGE2_BYTES);
        mma_step_km1(s, s + KM_BUF_BYTES, wm, wn, lane, acc);
    }
    epilogue(&out[(size_t)b * (H_ * H_) + (size_t)i0 * H_ + j0], H_, ETA_,
             wm, wn, lane, acc);
}

// ---------------------------------------------------------------------------
extern "C" void kernel_launch(void* const* d_in, const int* in_sizes, int n_in,
                              void* d_out, int out_size)
{
    const float* x = (const float*)d_in[0];   // (32,128,256)
    const float* W = (const float*)d_in[1];   // (1536,256)
    float* out = (float*)d_out;               // mem | keys | vals

    const int smem_k1 = 2 * RM_STAGE2_BYTES;      // 40960
    const int smem_k3 = 2 * RM_STAGE2_BYTES;      // 40960
    const int smem_k5 = 2 * KM_STAGE2_BYTES;      // 34816

    (void)cudaFuncSetAttribute(k1_gemm_in,
        cudaFuncAttributeMaxDynamicSharedMemorySize, smem_k1);
    (void)cudaFuncSetAttribute(k3_gemm_A,
        cudaFuncAttributeMaxDynamicSharedMemorySize, smem_k3);
    (void)cudaFuncSetAttribute(k5_gemm_mem,
        cudaFuncAttributeMaxDynamicSharedMemorySize, smem_k5);
    (void)cudaFuncSetAttribute(k4_scan_val,
        cudaFuncAttributeMaxDynamicSharedMemorySize, K4_SMEM);

    k0_convert<<<(XN_ + WN_ + 1023) / 1024, 256>>>(x, W);
    k1_gemm_in<<<dim3(12, 32), 256, smem_k1>>>();
    k2_scan_key<<<96, 256>>>(out);
    k3_gemm_A<<<dim3(6, 32), 256, smem_k3>>>();
    k4_scan_val<<<96, 256, K4_SMEM>>>(out);
    k5_gemm_mem<<<dim3(6, 6, 32), 256, smem_k5>>>(out);
}

// round 14
// speedup vs baseline: 2.4616x; 1.4922x over previous
#include <cuda_runtime.h>
#include <cuda_fp16.h>
#include <math.h>

// Problem constants
#define B_   32
#define T_   128
#define H_   768
#define IN_  256
#define H2_  1536

// exp(-1/20)
#define ALPHA_   0.951229424500714f
#define OMA_     0.048770575499286f
#define DTR_     0.951229424500714f
#define OMD_     0.048770575499286f
#define ETA_     0.1f
#define CIKV_    0.02f

// Output offsets (floats): mem | keys | vals
#define OUT_MEM_   0
#define OUT_KEYS_  18874368
#define OUT_VALS_  22020096

// Scratch (f32)
__device__ float g_i[B_ * T_ * H2_];          // only iv half (h>=768) is written/read
__device__ float g_Apart[6 * B_ * T_ * T_];

// fp16 operand arrays (all single-rounded)
__device__ __half g_xh[B_ * T_ * IN_];
__device__ __half g_Wh[H2_ * IN_];
__device__ __half g_keyh[B_ * T_ * H_];
__device__ __half g_ktrh[B_ * T_ * H_];
__device__ __half g_vtrh[B_ * T_ * H_];
__device__ __half g_Ah[B_ * T_ * T_];         // summed A, fp16

__device__ __forceinline__ float tanh_fast(float x) {
    float y;
    asm("tanh.approx.f32 %0, %1;" : "=f"(y) : "f"(x));
    return y;
}

// ---------------------------------------------------------------------------
// mma.sync helpers (fp16, f32 accum)
// ---------------------------------------------------------------------------
__device__ __forceinline__ void ldsm_x4(unsigned addr, unsigned& r0, unsigned& r1,
                                        unsigned& r2, unsigned& r3) {
    asm volatile("ldmatrix.sync.aligned.m8n8.x4.shared.b16 {%0,%1,%2,%3}, [%4];"
                 : "=r"(r0), "=r"(r1), "=r"(r2), "=r"(r3) : "r"(addr));
}
__device__ __forceinline__ void ldsm_x4t(unsigned addr, unsigned& r0, unsigned& r1,
                                         unsigned& r2, unsigned& r3) {
    asm volatile("ldmatrix.sync.aligned.m8n8.x4.trans.shared.b16 {%0,%1,%2,%3}, [%4];"
                 : "=r"(r0), "=r"(r1), "=r"(r2), "=r"(r3) : "r"(addr));
}
__device__ __forceinline__ void mma16816(float* c, unsigned a0, unsigned a1,
                                         unsigned a2, unsigned a3,
                                         unsigned b0, unsigned b1) {
    asm volatile(
        "mma.sync.aligned.m16n8k16.row.col.f32.f16.f16.f32 "
        "{%0,%1,%2,%3}, {%4,%5,%6,%7}, {%8,%9}, {%0,%1,%2,%3};"
        : "+f"(c[0]), "+f"(c[1]), "+f"(c[2]), "+f"(c[3])
        : "r"(a0), "r"(a1), "r"(a2), "r"(a3), "r"(b0), "r"(b1));
}

// cp.async helpers
__device__ __forceinline__ void cp16(unsigned dst, const void* src) {
    asm volatile("cp.async.cg.shared.global [%0], [%1], 16;" :: "r"(dst), "l"(src));
}
#define CP_COMMIT() asm volatile("cp.async.commit_group;")
#define CP_WAIT0()  asm volatile("cp.async.wait_group 0;" ::: "memory")

#define SRM 40    // smem stride (halves) row-major tiles (128 rows x 32 k)
#define SKM 136   // smem stride (halves) k-major tiles (32 k x 128 m)
#define RM_BUF_HALVES (128 * SRM)            // 5120
#define RM_BUF_BYTES  (RM_BUF_HALVES * 2)    // 10240
#define RM_STAGE2_BYTES (2 * RM_BUF_BYTES)   // Ah, Bh
#define KM_BUF_HALVES (32 * SKM)             // 4352
#define KM_BUF_BYTES  (KM_BUF_HALVES * 2)    // 8704
#define KM_STAGE2_BYTES (2 * KM_BUF_BYTES)

// Copy one row-major 128x32 fp16 tile into smem via cp.async.
__device__ __forceinline__ void cpa_rm1(unsigned dst, const __half* src,
                                        int ld, int tid)
{
#pragma unroll
    for (int l = 0; l < 2; l++) {
        int c = tid + l * 256;
        int row = c >> 2;
        int q   = c & 3;
        cp16(dst + (unsigned)(row * SRM * 2 + q * 16),
             (const char*)src + (size_t)row * ld * 2 + q * 16);
    }
}
// Copy one k-major 32x128 fp16 tile into smem.
__device__ __forceinline__ void cpa_km1(unsigned dst, const __half* src,
                                        int ld, int tid)
{
#pragma unroll
    for (int l = 0; l < 2; l++) {
        int c = tid + l * 256;
        int row = c >> 4;
        int q   = c & 15;
        cp16(dst + (unsigned)(row * SKM * 2 + q * 16),
             (const char*)src + (size_t)row * ld * 2 + q * 16);
    }
}

// BK=32 compute step, row-major tiles, single pass (K1/K3).
__device__ __forceinline__ void mma_step_rm1(
    unsigned bAh, unsigned bBh,
    int wm, int wn, int lane, float acc[4][4][4])
{
    const int lr = lane & 15;
    const int kh = (lane >> 4) * 8;
#pragma unroll
    for (int ks = 0; ks < 32; ks += 16) {
        unsigned ah[4][4], bh[4][2];
#pragma unroll
        for (int i = 0; i < 4; i++) {
            unsigned off = 2u * ((wm * 64 + i * 16 + lr) * SRM + ks + kh);
            ldsm_x4(bAh + off, ah[i][0], ah[i][1], ah[i][2], ah[i][3]);
        }
#pragma unroll
        for (int p = 0; p < 2; p++) {
            unsigned off = 2u * ((wn * 32 + p * 16 + lr) * SRM + ks + kh);
            unsigned r0, r1, r2, r3;
            ldsm_x4(bBh + off, r0, r1, r2, r3);
            bh[p * 2 + 0][0] = r0; bh[p * 2 + 0][1] = r2;
            bh[p * 2 + 1][0] = r1; bh[p * 2 + 1][1] = r3;
        }
#pragma unroll
        for (int i = 0; i < 4; i++)
#pragma unroll
            for (int j = 0; j < 4; j++)
                mma16816(acc[i][j], ah[i][0], ah[i][1], ah[i][2], ah[i][3],
                         bh[j][0], bh[j][1]);
    }
}

// BK=32 compute step, k-major tiles, single pass (K5).
__device__ __forceinline__ void mma_step_km1(
    unsigned bAh, unsigned bBh,
    int wm, int wn, int lane, float acc[4][4][4])
{
    const int krow = (lane & 7) + ((lane >> 4) << 3);
    const int mcol = ((lane >> 3) & 1) * 8;
#pragma unroll
    for (int ks = 0; ks < 32; ks += 16) {
        unsigned ah[4][4], bh[4][2];
#pragma unroll
        for (int i = 0; i < 4; i++) {
            unsigned off = 2u * ((ks + krow) * SKM + wm * 64 + i * 16 + mcol);
            ldsm_x4t(bAh + off, ah[i][0], ah[i][1], ah[i][2], ah[i][3]);
        }
#pragma unroll
        for (int p = 0; p < 2; p++) {
            unsigned off = 2u * ((ks + krow) * SKM + wn * 32 + p * 16 + mcol);
            unsigned r0, r1, r2, r3;
            ldsm_x4t(bBh + off, r0, r1, r2, r3);
            bh[p * 2 + 0][0] = r0; bh[p * 2 + 0][1] = r2;
            bh[p * 2 + 1][0] = r1; bh[p * 2 + 1][1] = r3;
        }
#pragma unroll
        for (int i = 0; i < 4; i++)
#pragma unroll
            for (int j = 0; j < 4; j++)
                mma16816(acc[i][j], ah[i][0], ah[i][1], ah[i][2], ah[i][3],
                         bh[j][0], bh[j][1]);
    }
}

// Epilogue: write 4x4 m16n8 tiles to gmem, scaled.
__device__ __forceinline__ void epilogue(float* dst, int ldc, float scale,
                                         int wm, int wn, int lane,
                                         float acc[4][4][4])
{
    const int r0 = lane >> 2;
    const int c0 = (lane & 3) * 2;
#pragma unroll
    for (int i = 0; i < 4; i++)
#pragma unroll
        for (int j = 0; j < 4; j++) {
            int row = wm * 64 + i * 16 + r0;
            int col = wn * 32 + j * 8 + c0;
            float2 v0 = make_float2(scale * acc[i][j][0], scale * acc[i][j][1]);
            float2 v1 = make_float2(scale * acc[i][j][2], scale * acc[i][j][3]);
            *(float2*)&dst[row * ldc + col] = v0;
            *(float2*)&dst[(row + 8) * ldc + col] = v1;
        }
}

// ---------------------------------------------------------------------------
// K0: round x and W to fp16
// ---------------------------------------------------------------------------
#define XN_ (B_ * T_ * IN_)   // 1048576
#define WN_ (H2_ * IN_)       // 393216

__global__ __launch_bounds__(256) void k0_convert(
    const float* __restrict__ x, const float* __restrict__ W)
{
    int i4 = (blockIdx.x * 256 + threadIdx.x) * 4;
    if (i4 < XN_) {
        float4 v = *(const float4*)&x[i4];
        g_xh[i4 + 0] = __float2half_rn(v.x);
        g_xh[i4 + 1] = __float2half_rn(v.y);
        g_xh[i4 + 2] = __float2half_rn(v.z);
        g_xh[i4 + 3] = __float2half_rn(v.w);
    } else if (i4 < XN_ + WN_) {
        int off = i4 - XN_;
        float4 v = *(const float4*)&W[off];
        g_Wh[off + 0] = __float2half_rn(v.x);
        g_Wh[off + 1] = __float2half_rn(v.y);
        g_Wh[off + 2] = __float2half_rn(v.z);
        g_Wh[off + 3] = __float2half_rn(v.w);
    }
}

// ---------------------------------------------------------------------------
// K1: i[m][n] = sum_k x[m][k]*W[n][k], M=4096 N=1536 K=256 (NK=8)
//     FUSED key scan: for ik tiles (bx<6), the m-tile = all t of one b, so
//     stage the 128x128 f32 tile in smem and run the key scan in-kernel
//     (identical f32 arithmetic to the old K2 -> bit-identical outputs).
//     iv tiles (bx>=6) write g_i as before. ik half of g_i is never written.
//     Dyn smem: 2-stage GEMM 40960 + scan buffer 128*SC1*4 = 108544B.
// ---------------------------------------------------------------------------
#define SC1 132

__global__ __launch_bounds__(256, 2) void k1_gemm_in(float* __restrict__ out)
{
    extern __shared__ __half dyn[];
    const int m0 = blockIdx.y * 128;
    const int n0 = blockIdx.x * 128;
    const int tid = threadIdx.x;
    const int warp = tid >> 5, lane = tid & 31;
    const int wm = warp >> 2, wn = warp & 3;

    unsigned sb = (unsigned)__cvta_generic_to_shared(dyn);

    float acc[4][4][4];
#pragma unroll
    for (int i = 0; i < 4; i++)
#pragma unroll
        for (int j = 0; j < 4; j++)
#pragma unroll
            for (int r = 0; r < 4; r++) acc[i][j][r] = 0.f;

    const __half* Ah = &g_xh[(size_t)m0 * IN_];
    const __half* Bh = &g_Wh[(size_t)n0 * IN_];

#define NK1 8
    {
        cpa_rm1(sb,                Ah, IN_, tid);
        cpa_rm1(sb + RM_BUF_BYTES, Bh, IN_, tid);
        CP_COMMIT();
    }
    for (int k = 0; k < NK1; k++) {
        CP_WAIT0();
        __syncthreads();
        if (k + 1 < NK1) {
            unsigned s1 = sb + (unsigned)(((k + 1) & 1) * RM_STAGE2_BYTES);
            cpa_rm1(s1,                Ah + (k + 1) * 32, IN_, tid);
            cpa_rm1(s1 + RM_BUF_BYTES, Bh + (k + 1) * 32, IN_, tid);
            CP_COMMIT();
        }
        unsigned s = sb + (unsigned)((k & 1) * RM_STAGE2_BYTES);
        mma_step_rm1(s, s + RM_BUF_BYTES, wm, wn, lane, acc);
    }

    if (blockIdx.x >= 6) {
        // iv half: plain epilogue to g_i
        epilogue(&g_i[(size_t)m0 * H2_ + n0], H2_, 1.f, wm, wn, lane, acc);
        return;
    }

    // ik half: stage tile (rows = t, cols = h-chunk) then run key scan
    float* sc = (float*)((char*)dyn + 2 * RM_STAGE2_BYTES);  // [128][SC1]
    {
        const int r0 = lane >> 2;
        const int c0 = (lane & 3) * 2;
#pragma unroll
        for (int i = 0; i < 4; i++)
#pragma unroll
            for (int j = 0; j < 4; j++) {
                int row = wm * 64 + i * 16 + r0;
                int col = wn * 32 + j * 8 + c0;
                sc[row * SC1 + col]           = acc[i][j][0];
                sc[row * SC1 + col + 1]       = acc[i][j][1];
                sc[(row + 8) * SC1 + col]     = acc[i][j][2];
                sc[(row + 8) * SC1 + col + 1] = acc[i][j][3];
            }
    }
    __syncthreads();

    if (tid < 128) {
        const int b = blockIdx.y;
        const int h = n0 + tid;
        const int base = (b * T_) * H_ + h;
        float* keyso = &out[OUT_KEYS_ + base];

        float kv = 0.f, ktr = 0.f;
#pragma unroll 4
        for (int t = 0; t < T_; t++) {
            kv = ALPHA_ * kv + OMA_ * sc[t * SC1 + tid];
            float key = tanh_fast(kv);
            ktr = DTR_ * ktr + OMD_ * key;
            keyso[t * H_] = key;
            g_keyh[base + t * H_] = __float2half_rn(key);
            g_ktrh[base + t * H_] = __float2half_rn(ktr);
        }
    }
}

// ---------------------------------------------------------------------------
// K3: Apart[p][b][t][s] = sum_{k in chunk p} key[b,t,k]*ktr[b,s,k]
//     grid (6,32). NK=4. Single-pass fp16.
// ---------------------------------------------------------------------------
__global__ __launch_bounds__(256, 2) void k3_gemm_A()
{
    extern __shared__ __half dyn[];
    const int p = blockIdx.x;
    const int b = blockIdx.y;
    const int tid = threadIdx.x;
    const int warp = tid >> 5, lane = tid & 31;
    const int wm = warp >> 2, wn = warp & 3;

    unsigned sb = (unsigned)__cvta_generic_to_shared(dyn);

    const size_t base = (size_t)b * T_ * H_ + p * 128;
    const __half* Ah = &g_keyh[base];
    const __half* Bh = &g_ktrh[base];

    float acc[4][4][4];
#pragma unroll
    for (int i = 0; i < 4; i++)
#pragma unroll
        for (int j = 0; j < 4; j++)
#pragma unroll
            for (int r = 0; r < 4; r++) acc[i][j][r] = 0.f;

#define NK3 4
    {
        cpa_rm1(sb,                Ah, H_, tid);
        cpa_rm1(sb + RM_BUF_BYTES, Bh, H_, tid);
        CP_COMMIT();
    }
    for (int k = 0; k < NK3; k++) {
        CP_WAIT0();
        __syncthreads();
        if (k + 1 < NK3) {
            unsigned s1 = sb + (unsigned)(((k + 1) & 1) * RM_STAGE2_BYTES);
            cpa_rm1(s1,                Ah + (k + 1) * 32, H_, tid);
            cpa_rm1(s1 + RM_BUF_BYTES, Bh + (k + 1) * 32, H_, tid);
            CP_COMMIT();
        }
        unsigned s = sb + (unsigned)((k & 1) * RM_STAGE2_BYTES);
        mma_step_rm1(s, s + RM_BUF_BYTES, wm, wn, lane, acc);
    }
    epilogue(&g_Apart[(size_t)(p * B_ + b) * (T_ * T_)], T_, 1.f, wm, wn, lane, acc);
}

// ---------------------------------------------------------------------------
// K35: sum the 6 K-split partials of A once per (b,t,s), write fp16 g_Ah.
//      Identical summation order to the old in-K4 sum -> bit-identical.
//      grid 512 x 256 threads, one float4 each.
// ---------------------------------------------------------------------------
__global__ __launch_bounds__(256) void k35_sum_A()
{
    int e = (blockIdx.x * 256 + threadIdx.x) * 4;   // < 524288
    float4 s = *(const float4*)&g_Apart[e];
#pragma unroll
    for (int p = 1; p < 6; p++) {
        float4 v = *(const float4*)&g_Apart[(size_t)p * B_ * T_ * T_ + e];
        s.x += v.x; s.y += v.y; s.z += v.z; s.w += v.w;
    }
    g_Ah[e + 0] = __float2half_rn(s.x);
    g_Ah[e + 1] = __float2half_rn(s.y);
    g_Ah[e + 2] = __float2half_rn(s.z);
    g_Ah[e + 3] = __float2half_rn(s.w);
}

// ---------------------------------------------------------------------------
// K4: value-side scan with tensor-core cross phase (R11 core).
//     A now cp.async'd from g_Ah (32KB) instead of summed in-kernel.
// ---------------------------------------------------------------------------
#define SA4 136   // A_s16 stride (halves)
#define SV4 264   // vtr16 stride (halves)
#define SP4 260   // p_s stride (floats)
#define K4_SMEM (128 * SA4 * 2 + 128 * SV4 * 2 + 16 * SP4 * 4)

__global__ __launch_bounds__(256) void k4_scan_val(float* __restrict__ out)
{
    extern __shared__ char sm4raw[];
    __half* A_s16 = (__half*)sm4raw;                              // [128][SA4]
    __half* vtr16 = (__half*)(sm4raw + 128 * SA4 * 2);            // [128][SV4]
    float*  p_s   = (float*)(sm4raw + 128 * SA4 * 2 + 128 * SV4 * 2); // [16][SP4]

    const int b    = blockIdx.x / 3;
    const int hb   = blockIdx.x % 3;
    const int tid  = threadIdx.x;
    const int warp = tid >> 5;
    const int lane = tid & 31;
    const int h    = hb * 256 + tid;

    unsigned aA = (unsigned)__cvta_generic_to_shared(A_s16);
    unsigned aV = (unsigned)__cvta_generic_to_shared(vtr16);

    // Load summed fp16 A tile (32KB) via cp.async into padded smem rows.
    {
        const char* src = (const char*)&g_Ah[(size_t)b * (T_ * T_)];
#pragma unroll
        for (int l = 0; l < 8; l++) {
            int c = tid + l * 256;        // 2048 16B chunks; 16 per 256B row
            int row = c >> 4, q = c & 15;
            cp16(aA + (unsigned)(row * SA4 * 2 + q * 16), src + (size_t)c * 16);
        }
        CP_COMMIT();
        CP_WAIT0();
    }
    __syncthreads();

    const float* ivp = &g_i[b * T_ * H2_ + H_ + h];
    const int gbase = (b * T_) * H_ + h;
    float* valso = &out[OUT_VALS_ + gbase];

    const int lr   = lane & 15;
    const int kh   = (lane >> 4) * 8;
    const int krow = (lane & 7) + ((lane >> 4) << 3);
    const int mcol = ((lane >> 3) & 1) * 8;
    const int r0w  = lane >> 2;
    const int c0w  = (lane & 3) * 2;

    float vv = 0.f, vtr = 0.f;

    for (int t0 = 0; t0 < T_; t0 += 16) {
        float iv_blk[16];
#pragma unroll
        for (int j = 0; j < 16; j++) iv_blk[j] = ivp[(t0 + j) * H2_];

        // ---- cross phase: mma over s in [0, t0) ----
        if (t0 > 0) {
            float c[4][4];
#pragma unroll
            for (int j = 0; j < 4; j++)
#pragma unroll
                for (int r = 0; r < 4; r++) c[j][r] = 0.f;

            for (int ks = 0; ks < t0; ks += 16) {
                unsigned af0, af1, af2, af3;
                ldsm_x4(aA + 2u * ((t0 + lr) * SA4 + ks + kh), af0, af1, af2, af3);
                unsigned bf[4][2];
#pragma unroll
                for (int p = 0; p < 2; p++) {
                    unsigned r0, r1, r2, r3;
                    ldsm_x4t(aV + 2u * ((ks + krow) * SV4 + warp * 32 + p * 16 + mcol),
                             r0, r1, r2, r3);
                    bf[p * 2 + 0][0] = r0; bf[p * 2 + 0][1] = r2;
                    bf[p * 2 + 1][0] = r1; bf[p * 2 + 1][1] = r3;
                }
#pragma unroll
                for (int j = 0; j < 4; j++)
                    mma16816(c[j], af0, af1, af2, af3, bf[j][0], bf[j][1]);
            }
#pragma unroll
            for (int j = 0; j < 4; j++) {
                int col = warp * 32 + j * 8 + c0w;
                p_s[r0w * SP4 + col]           = c[j][0];
                p_s[r0w * SP4 + col + 1]       = c[j][1];
                p_s[(r0w + 8) * SP4 + col]     = c[j][2];
                p_s[(r0w + 8) * SP4 + col + 1] = c[j][3];
            }
        }
        __syncthreads();

        // ---- intra phase: thread owns h = tid ----
        float vtr_blk[16];
#pragma unroll
        for (int j = 0; j < 16; j++) {
            const int t = t0 + j;
            float a = (t0 > 0) ? p_s[j * SP4 + tid] : 0.f;
#pragma unroll
            for (int sj = 0; sj < j; sj++)
                a = fmaf(__half2float(A_s16[t * SA4 + t0 + sj]), vtr_blk[sj], a);
            float ikv = CIKV_ * a;

            vv = ALPHA_ * vv + OMA_ * (iv_blk[j] + ikv);
            float val = tanh_fast(vv);
            vtr = DTR_ * vtr + OMD_ * val;
            vtr_blk[j] = vtr;

            valso[t * H_] = val;
            __half v16 = __float2half_rn(vtr);
            vtr16[t * SV4 + tid] = v16;
            g_vtrh[gbase + t * H_] = v16;
        }
        __syncthreads();
    }
}

// ---------------------------------------------------------------------------
// K5: mem[b][i][j] = eta * sum_s vtr[b,s,i]*ktr[b,s,j]
//     k-major fp16 single-pass, trans-ldmatrix. grid (6,6,32), NK=4.
// ---------------------------------------------------------------------------
__global__ __launch_bounds__(256, 2) void k5_gemm_mem(float* __restrict__ out)
{
    extern __shared__ __half dyn[];
    const int b  = blockIdx.z;
    const int i0 = blockIdx.y * 128;
    const int j0 = blockIdx.x * 128;
    const int tid = threadIdx.x;
    const int warp = tid >> 5, lane = tid & 31;
    const int wm = warp >> 2, wn = warp & 3;

    unsigned sb = (unsigned)__cvta_generic_to_shared(dyn);

    const size_t bb = (size_t)b * T_ * H_;
    const __half* Ah = &g_vtrh[bb + i0];
    const __half* Bh = &g_ktrh[bb + j0];

    float acc[4][4][4];
#pragma unroll
    for (int i = 0; i < 4; i++)
#pragma unroll
        for (int j = 0; j < 4; j++)
#pragma unroll
            for (int r = 0; r < 4; r++) acc[i][j][r] = 0.f;

#define NK5 4
    {
        cpa_km1(sb,                Ah, H_, tid);
        cpa_km1(sb + KM_BUF_BYTES, Bh, H_, tid);
        CP_COMMIT();
    }
    for (int k = 0; k < NK5; k++) {
        CP_WAIT0();
        __syncthreads();
        if (k + 1 < NK5) {
            unsigned s1 = sb + (unsigned)(((k + 1) & 1) * KM_STAGE2_BYTES);
            const size_t so = (size_t)(k + 1) * 32 * H_;
            cpa_km1(s1,                Ah + so, H_, tid);
            cpa_km1(s1 + KM_BUF_BYTES, Bh + so, H_, tid);
            CP_COMMIT();
        }
        unsigned s = sb + (unsigned)((k & 1) * KM_STAGE2_BYTES);
        mma_step_km1(s, s + KM_BUF_BYTES, wm, wn, lane, acc);
    }
    epilogue(&out[(size_t)b * (H_ * H_) + (size_t)i0 * H_ + j0], H_, ETA_,
             wm, wn, lane, acc);
}

// ---------------------------------------------------------------------------
extern "C" void kernel_launch(void* const* d_in, const int* in_sizes, int n_in,
                              void* d_out, int out_size)
{
    const float* x = (const float*)d_in[0];   // (32,128,256)
    const float* W = (const float*)d_in[1];   // (1536,256)
    float* out = (float*)d_out;               // mem | keys | vals

    const int smem_k1 = 2 * RM_STAGE2_BYTES + 128 * SC1 * 4;  // 108544
    const int smem_k3 = 2 * RM_STAGE2_BYTES;                  // 40960
    const int smem_k5 = 2 * KM_STAGE2_BYTES;                  // 34816

    (void)cudaFuncSetAttribute(k1_gemm_in,
        cudaFuncAttributeMaxDynamicSharedMemorySize, smem_k1);
    (void)cudaFuncSetAttribute(k3_gemm_A,
        cudaFuncAttributeMaxDynamicSharedMemorySize, smem_k3);
    (void)cudaFuncSetAttribute(k5_gemm_mem,
        cudaFuncAttributeMaxDynamicSharedMemorySize, smem_k5);
    (void)cudaFuncSetAttribute(k4_scan_val,
        cudaFuncAttributeMaxDynamicSharedMemorySize, K4_SMEM);

    k0_convert<<<(XN_ + WN_ + 1023) / 1024, 256>>>(x, W);
    k1_gemm_in<<<dim3(12, 32), 256, smem_k1>>>(out);
    k3_gemm_A<<<dim3(6, 32), 256, smem_k3>>>();
    k35_sum_A<<<512, 256>>>();
    k4_scan_val<<<96, 256, K4_SMEM>>>(out);
    k5_gemm_mem<<<dim3(6, 6, 32), 256, smem_k5>>>(out);
}

// round 15
// speedup vs baseline: 2.4635x; 1.0008x over previous
#include <cuda_runtime.h>
#include <cuda_fp16.h>
#include <math.h>

// Problem constants
#define B_   32
#define T_   128
#define H_   768
#define IN_  256
#define H2_  1536

// exp(-1/20)
#define ALPHA_   0.951229424500714f
#define OMA_     0.048770575499286f
#define DTR_     0.951229424500714f
#define OMD_     0.048770575499286f
#define ETA_     0.1f
#define CIKV_    0.02f

// Output offsets (floats): mem | keys | vals
#define OUT_MEM_   0
#define OUT_KEYS_  18874368
#define OUT_VALS_  22020096

// Scratch (f32)
__device__ float g_i[B_ * T_ * H2_];          // only iv half is written/read
__device__ float g_Apart[6 * B_ * T_ * T_];

// fp16 operand arrays (all single-rounded)
__device__ __half g_xh[B_ * T_ * IN_];
__device__ __half g_Wh[H2_ * IN_];
__device__ __half g_keyh[B_ * T_ * H_];
__device__ __half g_ktrh[B_ * T_ * H_];
__device__ __half g_vtrh[B_ * T_ * H_];
__device__ __half g_Ah[B_ * T_ * T_];         // summed A, fp16

__device__ __forceinline__ float tanh_fast(float x) {
    float y;
    asm("tanh.approx.f32 %0, %1;" : "=f"(y) : "f"(x));
    return y;
}

// ---------------------------------------------------------------------------
// mma.sync helpers (fp16, f32 accum)
// ---------------------------------------------------------------------------
__device__ __forceinline__ void ldsm_x4(unsigned addr, unsigned& r0, unsigned& r1,
                                        unsigned& r2, unsigned& r3) {
    asm volatile("ldmatrix.sync.aligned.m8n8.x4.shared.b16 {%0,%1,%2,%3}, [%4];"
                 : "=r"(r0), "=r"(r1), "=r"(r2), "=r"(r3) : "r"(addr));
}
__device__ __forceinline__ void ldsm_x4t(unsigned addr, unsigned& r0, unsigned& r1,
                                         unsigned& r2, unsigned& r3) {
    asm volatile("ldmatrix.sync.aligned.m8n8.x4.trans.shared.b16 {%0,%1,%2,%3}, [%4];"
                 : "=r"(r0), "=r"(r1), "=r"(r2), "=r"(r3) : "r"(addr));
}
__device__ __forceinline__ void mma16816(float* c, unsigned a0, unsigned a1,
                                         unsigned a2, unsigned a3,
                                         unsigned b0, unsigned b1) {
    asm volatile(
        "mma.sync.aligned.m16n8k16.row.col.f32.f16.f16.f32 "
        "{%0,%1,%2,%3}, {%4,%5,%6,%7}, {%8,%9}, {%0,%1,%2,%3};"
        : "+f"(c[0]), "+f"(c[1]), "+f"(c[2]), "+f"(c[3])
        : "r"(a0), "r"(a1), "r"(a2), "r"(a3), "r"(b0), "r"(b1));
}

// cp.async helpers
__device__ __forceinline__ void cp16(unsigned dst, const void* src) {
    asm volatile("cp.async.cg.shared.global [%0], [%1], 16;" :: "r"(dst), "l"(src));
}
#define CP_COMMIT() asm volatile("cp.async.commit_group;")
#define CP_WAIT0()  asm volatile("cp.async.wait_group 0;" ::: "memory")
#define CP_WAIT1()  asm volatile("cp.async.wait_group 1;" ::: "memory")

#define SRM 40    // smem stride (halves) row-major tiles (128 rows x 32 k)
#define SKM 136   // smem stride (halves) k-major tiles (32 k x 128 m)
#define RM_BUF_HALVES (128 * SRM)            // 5120
#define RM_BUF_BYTES  (RM_BUF_HALVES * 2)    // 10240
#define RM_STAGE_BYTES (2 * RM_BUF_BYTES)    // Ah, Bh per stage
#define KM_BUF_HALVES (32 * SKM)             // 4352
#define KM_BUF_BYTES  (KM_BUF_HALVES * 2)    // 8704
#define KM_STAGE_BYTES (2 * KM_BUF_BYTES)

// Copy one row-major 128x32 fp16 tile into smem via cp.async.
__device__ __forceinline__ void cpa_rm1(unsigned dst, const __half* src,
                                        int ld, int tid)
{
#pragma unroll
    for (int l = 0; l < 2; l++) {
        int c = tid + l * 256;
        int row = c >> 2;
        int q   = c & 3;
        cp16(dst + (unsigned)(row * SRM * 2 + q * 16),
             (const char*)src + (size_t)row * ld * 2 + q * 16);
    }
}
// Copy one k-major 32x128 fp16 tile into smem.
__device__ __forceinline__ void cpa_km1(unsigned dst, const __half* src,
                                        int ld, int tid)
{
#pragma unroll
    for (int l = 0; l < 2; l++) {
        int c = tid + l * 256;
        int row = c >> 4;
        int q   = c & 15;
        cp16(dst + (unsigned)(row * SKM * 2 + q * 16),
             (const char*)src + (size_t)row * ld * 2 + q * 16);
    }
}

// BK=32 compute step, row-major tiles, single pass (K1/K3).
__device__ __forceinline__ void mma_step_rm1(
    unsigned bAh, unsigned bBh,
    int wm, int wn, int lane, float acc[4][4][4])
{
    const int lr = lane & 15;
    const int kh = (lane >> 4) * 8;
#pragma unroll
    for (int ks = 0; ks < 32; ks += 16) {
        unsigned ah[4][4], bh[4][2];
#pragma unroll
        for (int i = 0; i < 4; i++) {
            unsigned off = 2u * ((wm * 64 + i * 16 + lr) * SRM + ks + kh);
            ldsm_x4(bAh + off, ah[i][0], ah[i][1], ah[i][2], ah[i][3]);
        }
#pragma unroll
        for (int p = 0; p < 2; p++) {
            unsigned off = 2u * ((wn * 32 + p * 16 + lr) * SRM + ks + kh);
            unsigned r0, r1, r2, r3;
            ldsm_x4(bBh + off, r0, r1, r2, r3);
            bh[p * 2 + 0][0] = r0; bh[p * 2 + 0][1] = r2;
            bh[p * 2 + 1][0] = r1; bh[p * 2 + 1][1] = r3;
        }
#pragma unroll
        for (int i = 0; i < 4; i++)
#pragma unroll
            for (int j = 0; j < 4; j++)
                mma16816(acc[i][j], ah[i][0], ah[i][1], ah[i][2], ah[i][3],
                         bh[j][0], bh[j][1]);
    }
}

// BK=32 compute step, k-major tiles, single pass (K5).
__device__ __forceinline__ void mma_step_km1(
    unsigned bAh, unsigned bBh,
    int wm, int wn, int lane, float acc[4][4][4])
{
    const int krow = (lane & 7) + ((lane >> 4) << 3);
    const int mcol = ((lane >> 3) & 1) * 8;
#pragma unroll
    for (int ks = 0; ks < 32; ks += 16) {
        unsigned ah[4][4], bh[4][2];
#pragma unroll
        for (int i = 0; i < 4; i++) {
            unsigned off = 2u * ((ks + krow) * SKM + wm * 64 + i * 16 + mcol);
            ldsm_x4t(bAh + off, ah[i][0], ah[i][1], ah[i][2], ah[i][3]);
        }
#pragma unroll
        for (int p = 0; p < 2; p++) {
            unsigned off = 2u * ((ks + krow) * SKM + wn * 32 + p * 16 + mcol);
            unsigned r0, r1, r2, r3;
            ldsm_x4t(bBh + off, r0, r1, r2, r3);
            bh[p * 2 + 0][0] = r0; bh[p * 2 + 0][1] = r2;
            bh[p * 2 + 1][0] = r1; bh[p * 2 + 1][1] = r3;
        }
#pragma unroll
        for (int i = 0; i < 4; i++)
#pragma unroll
            for (int j = 0; j < 4; j++)
                mma16816(acc[i][j], ah[i][0], ah[i][1], ah[i][2], ah[i][3],
                         bh[j][0], bh[j][1]);
    }
}

// Epilogue: write 4x4 m16n8 tiles to gmem, scaled.
__device__ __forceinline__ void epilogue(float* dst, int ldc, float scale,
                                         int wm, int wn, int lane,
                                         float acc[4][4][4])
{
    const int r0 = lane >> 2;
    const int c0 = (lane & 3) * 2;
#pragma unroll
    for (int i = 0; i < 4; i++)
#pragma unroll
        for (int j = 0; j < 4; j++) {
            int row = wm * 64 + i * 16 + r0;
            int col = wn * 32 + j * 8 + c0;
            float2 v0 = make_float2(scale * acc[i][j][0], scale * acc[i][j][1]);
            float2 v1 = make_float2(scale * acc[i][j][2], scale * acc[i][j][3]);
            *(float2*)&dst[row * ldc + col] = v0;
            *(float2*)&dst[(row + 8) * ldc + col] = v1;
        }
}

// ---------------------------------------------------------------------------
// K0: round x and W to fp16
// ---------------------------------------------------------------------------
#define XN_ (B_ * T_ * IN_)   // 1048576
#define WN_ (H2_ * IN_)       // 393216

__global__ __launch_bounds__(256) void k0_convert(
    const float* __restrict__ x, const float* __restrict__ W)
{
    int i4 = (blockIdx.x * 256 + threadIdx.x) * 4;
    if (i4 < XN_) {
        float4 v = *(const float4*)&x[i4];
        g_xh[i4 + 0] = __float2half_rn(v.x);
        g_xh[i4 + 1] = __float2half_rn(v.y);
        g_xh[i4 + 2] = __float2half_rn(v.z);
        g_xh[i4 + 3] = __float2half_rn(v.w);
    } else if (i4 < XN_ + WN_) {
        int off = i4 - XN_;
        float4 v = *(const float4*)&W[off];
        g_Wh[off + 0] = __float2half_rn(v.x);
        g_Wh[off + 1] = __float2half_rn(v.y);
        g_Wh[off + 2] = __float2half_rn(v.z);
        g_Wh[off + 3] = __float2half_rn(v.w);
    }
}

// ---------------------------------------------------------------------------
// K1: i = x@W^T (M=4096 N=1536 K=256, NK=8), 3-stage cp.async pipeline,
//     FUSED key scan for ik tiles (bx<6); scan buffer ALIASES the stage smem
//     (GEMM done before scan). iv tiles write g_i. Dyn smem 67584B.
// ---------------------------------------------------------------------------
#define SC1 132

__global__ __launch_bounds__(256, 2) void k1_gemm_in(float* __restrict__ out)
{
    extern __shared__ __half dyn[];
    const int m0 = blockIdx.y * 128;
    const int n0 = blockIdx.x * 128;
    const int tid = threadIdx.x;
    const int warp = tid >> 5, lane = tid & 31;
    const int wm = warp >> 2, wn = warp & 3;

    unsigned sb = (unsigned)__cvta_generic_to_shared(dyn);

    float acc[4][4][4];
#pragma unroll
    for (int i = 0; i < 4; i++)
#pragma unroll
        for (int j = 0; j < 4; j++)
#pragma unroll
            for (int r = 0; r < 4; r++) acc[i][j][r] = 0.f;

    const __half* Ah = &g_xh[(size_t)m0 * IN_];
    const __half* Bh = &g_Wh[(size_t)n0 * IN_];

#define NK1 8
    // prologue: stages 0 and 1 in flight
    cpa_rm1(sb,                 Ah, IN_, tid);
    cpa_rm1(sb + RM_BUF_BYTES,  Bh, IN_, tid);
    CP_COMMIT();
    cpa_rm1(sb + RM_STAGE_BYTES,                Ah + 32, IN_, tid);
    cpa_rm1(sb + RM_STAGE_BYTES + RM_BUF_BYTES, Bh + 32, IN_, tid);
    CP_COMMIT();

    for (int k = 0; k < NK1; k++) {
        if (k + 1 < NK1) CP_WAIT1(); else CP_WAIT0();
        __syncthreads();
        if (k + 2 < NK1) {
            unsigned s2 = sb + (unsigned)(((k + 2) % 3) * RM_STAGE_BYTES);
            cpa_rm1(s2,                Ah + (k + 2) * 32, IN_, tid);
            cpa_rm1(s2 + RM_BUF_BYTES, Bh + (k + 2) * 32, IN_, tid);
            CP_COMMIT();
        }
        unsigned s = sb + (unsigned)((k % 3) * RM_STAGE_BYTES);
        mma_step_rm1(s, s + RM_BUF_BYTES, wm, wn, lane, acc);
    }

    if (blockIdx.x >= 6) {
        epilogue(&g_i[(size_t)m0 * H2_ + n0], H2_, 1.f, wm, wn, lane, acc);
        return;
    }

    // ik half: stage tile in smem (aliases stage buffers; GEMM complete)
    __syncthreads();
    float* sc = (float*)dyn;  // [128][SC1]
    {
        const int r0 = lane >> 2;
        const int c0 = (lane & 3) * 2;
#pragma unroll
        for (int i = 0; i < 4; i++)
#pragma unroll
            for (int j = 0; j < 4; j++) {
                int row = wm * 64 + i * 16 + r0;
                int col = wn * 32 + j * 8 + c0;
                sc[row * SC1 + col]           = acc[i][j][0];
                sc[row * SC1 + col + 1]       = acc[i][j][1];
                sc[(row + 8) * SC1 + col]     = acc[i][j][2];
                sc[(row + 8) * SC1 + col + 1] = acc[i][j][3];
            }
    }
    __syncthreads();

    if (tid < 128) {
        const int b = blockIdx.y;
        const int h = n0 + tid;
        const int base = (b * T_) * H_ + h;
        float* keyso = &out[OUT_KEYS_ + base];

        float kv = 0.f, ktr = 0.f;
#pragma unroll 4
        for (int t = 0; t < T_; t++) {
            kv = ALPHA_ * kv + OMA_ * sc[t * SC1 + tid];
            float key = tanh_fast(kv);
            ktr = DTR_ * ktr + OMD_ * key;
            keyso[t * H_] = key;
            g_keyh[base + t * H_] = __float2half_rn(key);
            g_ktrh[base + t * H_] = __float2half_rn(ktr);
        }
    }
}

// ---------------------------------------------------------------------------
// K3: Apart[p][b][t][s] = sum_{k in chunk p} key[b,t,k]*ktr[b,s,k]
//     grid (6,32). NK=4. Single-pass fp16, 3-stage pipeline.
// ---------------------------------------------------------------------------
__global__ __launch_bounds__(256, 2) void k3_gemm_A()
{
    extern __shared__ __half dyn[];
    const int p = blockIdx.x;
    const int b = blockIdx.y;
    const int tid = threadIdx.x;
    const int warp = tid >> 5, lane = tid & 31;
    const int wm = warp >> 2, wn = warp & 3;

    unsigned sb = (unsigned)__cvta_generic_to_shared(dyn);

    const size_t base = (size_t)b * T_ * H_ + p * 128;
    const __half* Ah = &g_keyh[base];
    const __half* Bh = &g_ktrh[base];

    float acc[4][4][4];
#pragma unroll
    for (int i = 0; i < 4; i++)
#pragma unroll
        for (int j = 0; j < 4; j++)
#pragma unroll
            for (int r = 0; r < 4; r++) acc[i][j][r] = 0.f;

#define NK3 4
    cpa_rm1(sb,                Ah, H_, tid);
    cpa_rm1(sb + RM_BUF_BYTES, Bh, H_, tid);
    CP_COMMIT();
    cpa_rm1(sb + RM_STAGE_BYTES,                Ah + 32, H_, tid);
    cpa_rm1(sb + RM_STAGE_BYTES + RM_BUF_BYTES, Bh + 32, H_, tid);
    CP_COMMIT();

    for (int k = 0; k < NK3; k++) {
        if (k + 1 < NK3) CP_WAIT1(); else CP_WAIT0();
        __syncthreads();
        if (k + 2 < NK3) {
            unsigned s2 = sb + (unsigned)(((k + 2) % 3) * RM_STAGE_BYTES);
            cpa_rm1(s2,                Ah + (k + 2) * 32, H_, tid);
            cpa_rm1(s2 + RM_BUF_BYTES, Bh + (k + 2) * 32, H_, tid);
            CP_COMMIT();
        }
        unsigned s = sb + (unsigned)((k % 3) * RM_STAGE_BYTES);
        mma_step_rm1(s, s + RM_BUF_BYTES, wm, wn, lane, acc);
    }
    epilogue(&g_Apart[(size_t)(p * B_ + b) * (T_ * T_)], T_, 1.f, wm, wn, lane, acc);
}

// ---------------------------------------------------------------------------
// K35: sum the 6 K-split partials once, write fp16 g_Ah. Same summation
//      order as before -> bit-identical. 8 elems/thread for MLP.
//      grid 256 x 256 threads.
// ---------------------------------------------------------------------------
__global__ __launch_bounds__(256) void k35_sum_A()
{
    int e = (blockIdx.x * 256 + threadIdx.x) * 8;   // < 524288
    float4 s0 = *(const float4*)&g_Apart[e];
    float4 s1 = *(const float4*)&g_Apart[e + 4];
#pragma unroll
    for (int p = 1; p < 6; p++) {
        float4 v0 = *(const float4*)&g_Apart[(size_t)p * B_ * T_ * T_ + e];
        float4 v1 = *(const float4*)&g_Apart[(size_t)p * B_ * T_ * T_ + e + 4];
        s0.x += v0.x; s0.y += v0.y; s0.z += v0.z; s0.w += v0.w;
        s1.x += v1.x; s1.y += v1.y; s1.z += v1.z; s1.w += v1.w;
    }
    __half h[8];
    h[0] = __float2half_rn(s0.x); h[1] = __float2half_rn(s0.y);
    h[2] = __float2half_rn(s0.z); h[3] = __float2half_rn(s0.w);
    h[4] = __float2half_rn(s1.x); h[5] = __float2half_rn(s1.y);
    h[6] = __float2half_rn(s1.z); h[7] = __float2half_rn(s1.w);
    *(uint4*)&g_Ah[e] = *(const uint4*)h;
}

// ---------------------------------------------------------------------------
// K4: value-side scan with tensor-core cross phase (proven core).
// ---------------------------------------------------------------------------
#define SA4 136   // A_s16 stride (halves)
#define SV4 264   // vtr16 stride (halves)
#define SP4 260   // p_s stride (floats)
#define K4_SMEM (128 * SA4 * 2 + 128 * SV4 * 2 + 16 * SP4 * 4)

__global__ __launch_bounds__(256) void k4_scan_val(float* __restrict__ out)
{
    extern __shared__ char sm4raw[];
    __half* A_s16 = (__half*)sm4raw;                              // [128][SA4]
    __half* vtr16 = (__half*)(sm4raw + 128 * SA4 * 2);            // [128][SV4]
    float*  p_s   = (float*)(sm4raw + 128 * SA4 * 2 + 128 * SV4 * 2); // [16][SP4]

    const int b    = blockIdx.x / 3;
    const int hb   = blockIdx.x % 3;
    const int tid  = threadIdx.x;
    const int warp = tid >> 5;
    const int lane = tid & 31;
    const int h    = hb * 256 + tid;

    unsigned aA = (unsigned)__cvta_generic_to_shared(A_s16);
    unsigned aV = (unsigned)__cvta_generic_to_shared(vtr16);

    // Load summed fp16 A tile (32KB) via cp.async into padded smem rows.
    {
        const char* src = (const char*)&g_Ah[(size_t)b * (T_ * T_)];
#pragma unroll
        for (int l = 0; l < 8; l++) {
            int c = tid + l * 256;
            int row = c >> 4, q = c & 15;
            cp16(aA + (unsigned)(row * SA4 * 2 + q * 16), src + (size_t)c * 16);
        }
        CP_COMMIT();
        CP_WAIT0();
    }
    __syncthreads();

    const float* ivp = &g_i[b * T_ * H2_ + H_ + h];
    const int gbase = (b * T_) * H_ + h;
    float* valso = &out[OUT_VALS_ + gbase];

    const int lr   = lane & 15;
    const int kh   = (lane >> 4) * 8;
    const int krow = (lane & 7) + ((lane >> 4) << 3);
    const int mcol = ((lane >> 3) & 1) * 8;
    const int r0w  = lane >> 2;
    const int c0w  = (lane & 3) * 2;

    float vv = 0.f, vtr = 0.f;

    for (int t0 = 0; t0 < T_; t0 += 16) {
        float iv_blk[16];
#pragma unroll
        for (int j = 0; j < 16; j++) iv_blk[j] = ivp[(t0 + j) * H2_];

        if (t0 > 0) {
            float c[4][4];
#pragma unroll
            for (int j = 0; j < 4; j++)
#pragma unroll
                for (int r = 0; r < 4; r++) c[j][r] = 0.f;

            for (int ks = 0; ks < t0; ks += 16) {
                unsigned af0, af1, af2, af3;
                ldsm_x4(aA + 2u * ((t0 + lr) * SA4 + ks + kh), af0, af1, af2, af3);
                unsigned bf[4][2];
#pragma unroll
                for (int p = 0; p < 2; p++) {
                    unsigned r0, r1, r2, r3;
                    ldsm_x4t(aV + 2u * ((ks + krow) * SV4 + warp * 32 + p * 16 + mcol),
                             r0, r1, r2, r3);
                    bf[p * 2 + 0][0] = r0; bf[p * 2 + 0][1] = r2;
                    bf[p * 2 + 1][0] = r1; bf[p * 2 + 1][1] = r3;
                }
#pragma unroll
                for (int j = 0; j < 4; j++)
                    mma16816(c[j], af0, af1, af2, af3, bf[j][0], bf[j][1]);
            }
#pragma unroll
            for (int j = 0; j < 4; j++) {
                int col = warp * 32 + j * 8 + c0w;
                p_s[r0w * SP4 + col]           = c[j][0];
                p_s[r0w * SP4 + col + 1]       = c[j][1];
                p_s[(r0w + 8) * SP4 + col]     = c[j][2];
                p_s[(r0w + 8) * SP4 + col + 1] = c[j][3];
            }
        }
        __syncthreads();

        float vtr_blk[16];
#pragma unroll
        for (int j = 0; j < 16; j++) {
            const int t = t0 + j;
            float a = (t0 > 0) ? p_s[j * SP4 + tid] : 0.f;
#pragma unroll
            for (int sj = 0; sj < j; sj++)
                a = fmaf(__half2float(A_s16[t * SA4 + t0 + sj]), vtr_blk[sj], a);
            float ikv = CIKV_ * a;

            vv = ALPHA_ * vv + OMA_ * (iv_blk[j] + ikv);
            float val = tanh_fast(vv);
            vtr = DTR_ * vtr + OMD_ * val;
            vtr_blk[j] = vtr;

            valso[t * H_] = val;
            __half v16 = __float2half_rn(vtr);
            vtr16[t * SV4 + tid] = v16;
            g_vtrh[gbase + t * H_] = v16;
        }
        __syncthreads();
    }
}

// ---------------------------------------------------------------------------
// K5: mem[b][i][j] = eta * sum_s vtr[b,s,i]*ktr[b,s,j]
//     k-major fp16 single-pass, trans-ldmatrix, 3-stage pipeline.
//     grid (6,6,32), NK=4.
// ---------------------------------------------------------------------------
__global__ __launch_bounds__(256, 2) void k5_gemm_mem(float* __restrict__ out)
{
    extern __shared__ __half dyn[];
    const int b  = blockIdx.z;
    const int i0 = blockIdx.y * 128;
    const int j0 = blockIdx.x * 128;
    const int tid = threadIdx.x;
    const int warp = tid >> 5, lane = tid & 31;
    const int wm = warp >> 2, wn = warp & 3;

    unsigned sb = (unsigned)__cvta_generic_to_shared(dyn);

    const size_t bb = (size_t)b * T_ * H_;
    const __half* Ah = &g_vtrh[bb + i0];
    const __half* Bh = &g_ktrh[bb + j0];

    float acc[4][4][4];
#pragma unroll
    for (int i = 0; i < 4; i++)
#pragma unroll
        for (int j = 0; j < 4; j++)
#pragma unroll
            for (int r = 0; r < 4; r++) acc[i][j][r] = 0.f;

#define NK5 4
    cpa_km1(sb,                Ah, H_, tid);
    cpa_km1(sb + KM_BUF_BYTES, Bh, H_, tid);
    CP_COMMIT();
    cpa_km1(sb + KM_STAGE_BYTES,                Ah + (size_t)32 * H_, H_, tid);
    cpa_km1(sb + KM_STAGE_BYTES + KM_BUF_BYTES, Bh + (size_t)32 * H_, H_, tid);
    CP_COMMIT();

    for (int k = 0; k < NK5; k++) {
        if (k + 1 < NK5) CP_WAIT1(); else CP_WAIT0();
        __syncthreads();
        if (k + 2 < NK5) {
            unsigned s2 = sb + (unsigned)(((k + 2) % 3) * KM_STAGE_BYTES);
            const size_t so = (size_t)(k + 2) * 32 * H_;
            cpa_km1(s2,                Ah + so, H_, tid);
            cpa_km1(s2 + KM_BUF_BYTES, Bh + so, H_, tid);
            CP_COMMIT();
        }
        unsigned s = sb + (unsigned)((k % 3) * KM_STAGE_BYTES);
        mma_step_km1(s, s + KM_BUF_BYTES, wm, wn, lane, acc);
    }
    epilogue(&out[(size_t)b * (H_ * H_) + (size_t)i0 * H_ + j0], H_, ETA_,
             wm, wn, lane, acc);
}

// ---------------------------------------------------------------------------
extern "C" void kernel_launch(void* const* d_in, const int* in_sizes, int n_in,
                              void* d_out, int out_size)
{
    const float* x = (const float*)d_in[0];   // (32,128,256)
    const float* W = (const float*)d_in[1];   // (1536,256)
    float* out = (float*)d_out;               // mem | keys | vals

    const int smem_k1 = 128 * SC1 * 4;            // 67584 (>= 3*RM_STAGE_BYTES)
    const int smem_k3 = 3 * RM_STAGE_BYTES;       // 61440
    const int smem_k5 = 3 * KM_STAGE_BYTES;       // 52224

    (void)cudaFuncSetAttribute(k1_gemm_in,
        cudaFuncAttributeMaxDynamicSharedMemorySize, smem_k1);
    (void)cudaFuncSetAttribute(k3_gemm_A,
        cudaFuncAttributeMaxDynamicSharedMemorySize, smem_k3);
    (void)cudaFuncSetAttribute(k5_gemm_mem,
        cudaFuncAttributeMaxDynamicSharedMemorySize, smem_k5);
    (void)cudaFuncSetAttribute(k4_scan_val,
        cudaFuncAttributeMaxDynamicSharedMemorySize, K4_SMEM);

    k0_convert<<<(XN_ + WN_ + 1023) / 1024, 256>>>(x, W);
    k1_gemm_in<<<dim3(12, 32), 256, smem_k1>>>(out);
    k3_gemm_A<<<dim3(6, 32), 256, smem_k3>>>();
    k35_sum_A<<<256, 256>>>();
    k4_scan_val<<<96, 256, K4_SMEM>>>(out);
    k5_gemm_mem<<<dim3(6, 6, 32), 256, smem_k5>>>(out);
}